// round 1
// baseline (speedup 1.0000x reference)
#include <cuda_runtime.h>
#include <math.h>

#define BB 64
#define TT 12
#define BT 768          // BB*TT
#define NN 512
#define HH 64
#define TDD 32
#define O1 128
#define O2 64

// ---------------- scratch (device globals; no allocation) ----------------
__device__ float g_A [NN*NN];                 // adjacency (row-softmax)
__device__ float g_de[BT*NN*HH];              // de_input
__device__ float g_y [BT*NN*HH];              // z * de_input
__device__ float g_rg[BT*NN*HH];              // reset gate
__device__ float g_p1[BT*NN*HH];              // A @ x
__device__ float g_p2[BT*NN*HH];              // A @ (A @ x)
__device__ float g_W1[BT*3*65*O1];            // per-(b,t) gcn1 weights (full 65 rows)
__device__ float g_W2[BT*3*65*O2];            // per-(b,t) gcn2 weights
__device__ float g_b1[BT*O1];
__device__ float g_b2[BT*O2];

// ---------------- adjacency: A = softmax_row(relu(E E^T)) ----------------
__global__ void k_adj(const float* __restrict__ E) {
    int n = blockIdx.x;
    int m = threadIdx.x;               // 512 threads
    __shared__ float en[16];
    __shared__ float red[512];
    if (m < 16) en[m] = E[n*16 + m];
    __syncthreads();
    float s = 0.f;
    #pragma unroll
    for (int j = 0; j < 16; j++) s = fmaf(en[j], E[m*16 + j], s);
    s = fmaxf(s, 0.f);
    red[m] = s; __syncthreads();
    for (int off = 256; off > 0; off >>= 1) {
        if (m < off) red[m] = fmaxf(red[m], red[m+off]);
        __syncthreads();
    }
    float mx = red[0]; __syncthreads();
    float e = expf(s - mx);
    red[m] = e; __syncthreads();
    for (int off = 256; off > 0; off >>= 1) {
        if (m < off) red[m] += red[m+off];
        __syncthreads();
    }
    g_A[n*NN + m] = e / red[0];
}

// ---------------- propagation: Y[p][n][c] = sum_m A[n][m] X[p][m][c] ------
// Block: 64 rows x 128 cols (2 panels of 64). 256 thr, 4x8 microtile.
// mode 1: de->p1   mode 2: p1->p2   mode 3: y->p1
__global__ void k_prop(int mode) {
    const float* X; float* Y;
    if (mode == 1)      { X = g_de; Y = g_p1; }
    else if (mode == 2) { X = g_p1; Y = g_p2; }
    else                { X = g_y;  Y = g_p1; }
    const long long ps = (long long)NN*HH;

    __shared__ float As[16][65];
    __shared__ float Bs[16][128];
    int n0 = blockIdx.x * 64;
    int p0 = blockIdx.y * 2;
    const float* X0 = X + p0*ps;
    const float* X1 = X0 + ps;
    float*       Y0 = Y + p0*ps;
    float*       Y1 = Y0 + ps;
    int tid = threadIdx.x;
    int tx = tid & 15, ty = tid >> 4;

    float acc[4][8];
    #pragma unroll
    for (int i=0;i<4;i++)
        #pragma unroll
        for (int j=0;j<8;j++) acc[i][j]=0.f;

    for (int m0 = 0; m0 < NN; m0 += 16) {
        #pragma unroll
        for (int p=0;p<4;p++) {            // 1024 floats of A
            int idx = tid + p*256;
            int kk = idx & 15, i = idx >> 4;
            As[kk][i] = g_A[(n0+i)*NN + m0 + kk];
        }
        #pragma unroll
        for (int p=0;p<8;p++) {            // 2048 floats of X (2 panels)
            int idx = tid + p*256;
            int c = idx & 63, kk = (idx >> 6) & 15, bl = idx >> 10;
            const float* Xp = bl ? X1 : X0;
            Bs[kk][bl*64 + c] = Xp[(m0+kk)*HH + c];
        }
        __syncthreads();
        #pragma unroll
        for (int kk=0; kk<16; kk++) {
            float av[4];
            #pragma unroll
            for (int i=0;i<4;i++) av[i] = As[kk][ty*4+i];
            float4 bA = *(const float4*)&Bs[kk][tx*8];
            float4 bB = *(const float4*)&Bs[kk][tx*8+4];
            float bv[8] = {bA.x,bA.y,bA.z,bA.w,bB.x,bB.y,bB.z,bB.w};
            #pragma unroll
            for (int i=0;i<4;i++)
                #pragma unroll
                for (int j=0;j<8;j++) acc[i][j] = fmaf(av[i], bv[j], acc[i][j]);
        }
        __syncthreads();
    }
    float* Yp = (tx >= 8) ? Y1 : Y0;
    int c0 = (tx & 7) * 8;
    #pragma unroll
    for (int i=0;i<4;i++) {
        float* dst = Yp + (long long)(n0 + ty*4 + i)*HH + c0;
        *(float4*)(dst)   = make_float4(acc[i][0],acc[i][1],acc[i][2],acc[i][3]);
        *(float4*)(dst+4) = make_float4(acc[i][4],acc[i][5],acc[i][6],acc[i][7]);
    }
}

// ---------------- temporal attention -> de_input -------------------------
__global__ void k_attn(const float* __restrict__ hn, const float* __restrict__ ne1,
                       const float* __restrict__ ne2,
                       const float* __restrict__ Wq, const float* __restrict__ bq,
                       const float* __restrict__ Wk, const float* __restrict__ bk,
                       const float* __restrict__ Wv, const float* __restrict__ bv,
                       const float* __restrict__ taw, const float* __restrict__ tab) {
    int n = blockIdx.x, b = blockIdx.y;
    int tid = threadIdx.x;     // 128
    __shared__ float xs[64], sp[32], sq[TT*TDD], ks[64], vs[64], qs[TT*64], lg[96];

    if (tid < 64)            xs[tid]    = hn[((long long)b*NN + n)*HH + tid];
    else if (tid < 96)       sp[tid-64] = ne1[b*TT*TDD + 11*TDD + (tid-64)];
    for (int i = tid; i < TT*TDD; i += 128) sq[i] = ne2[b*TT*TDD + i];
    __syncthreads();

    { // k (threads 0..63) and v (64..127)
        int h = tid & 63;
        const float* W  = (tid < 64) ? Wk : Wv;
        const float* bb = (tid < 64) ? bk : bv;
        float a = bb[h];
        #pragma unroll
        for (int j=0;j<32;j++) a = fmaf(sp[j], W[j*64+h], a);
        #pragma unroll
        for (int j=0;j<64;j++) a = fmaf(xs[j], W[(32+j)*64+h], a);
        a = fmaxf(a, 0.f);
        if (tid < 64) ks[h] = a; else vs[h] = a;
    }
    for (int idx = tid; idx < TT*64; idx += 128) {   // q
        int t = idx >> 6, h = idx & 63;
        float a = bq[h];
        #pragma unroll
        for (int j=0;j<32;j++) a = fmaf(sq[t*32+j], Wq[j*64+h], a);
        #pragma unroll
        for (int j=0;j<64;j++) a = fmaf(xs[j], Wq[(32+j)*64+h], a);
        qs[idx] = fmaxf(a, 0.f);
    }
    __syncthreads();
    if (tid < 96) {                                  // logits per (head, t)
        int d = tid / 12, t = tid % 12;
        float a = 0.f;
        #pragma unroll
        for (int c=0;c<8;c++) a = fmaf(qs[t*64 + d*8 + c], ks[d*8+c], a);
        lg[d*12+t] = a;
    }
    __syncthreads();
    if (tid < 8) {                                   // softmax over t
        int d = tid;
        float mx = -1e30f;
        for (int t=0;t<12;t++) mx = fmaxf(mx, lg[d*12+t]);
        float s = 0.f;
        for (int t=0;t<12;t++){ float e = expf(lg[d*12+t]-mx); lg[d*12+t]=e; s+=e; }
        float inv = 1.f/s;
        for (int t=0;t<12;t++) lg[d*12+t] *= inv;
    }
    __syncthreads();
    for (int idx = tid; idx < TT*64; idx += 128) {   // combine + ta_w projection
        int t = idx >> 6, h = idx & 63;
        float a = tab[h];
        #pragma unroll
        for (int i=0;i<64;i++) {
            a = fmaf(xs[i], taw[i*64 + h], a);
            float o = lg[(i>>3)*12 + t] * vs[i];
            a = fmaf(o, taw[4096 + i*64 + h], a);
        }
        g_de[((long long)(b*12+t)*NN + n)*HH + h] = a;
    }
}

// ---------------- per-(b,t) weights: C[768][Nc] = temb@B + bias ----------
// mode 0: gwp->g_W1 (Nc=24960)  1: uwp->g_W2 (12480)  2: gbp->g_b1 (128)  3: ubp->g_b2 (64)
__global__ void k_wgemm(const float* __restrict__ Am, const float* __restrict__ Bm,
                        const float* __restrict__ bias, int mode) {
    float* C; int Nc;
    if (mode == 0)      { C = g_W1; Nc = 3*65*O1; }
    else if (mode == 1) { C = g_W2; Nc = 3*65*O2; }
    else if (mode == 2) { C = g_b1; Nc = O1; }
    else                { C = g_b2; Nc = O2; }

    __shared__ float At[32][65];
    __shared__ float Bt[32][64];
    int q0 = blockIdx.x * 64;
    int m0 = blockIdx.y * 64;
    int tid = threadIdx.x;
    int tx = tid & 15, ty = tid >> 4;
    #pragma unroll
    for (int p=0;p<8;p++) {
        int idx = tid + p*256;
        int d = idx & 31, m = idx >> 5;
        At[d][m] = Am[(m0+m)*32 + d];
    }
    #pragma unroll
    for (int p=0;p<8;p++) {
        int idx = tid + p*256;
        int q = idx & 63, d = idx >> 6;
        Bt[d][q] = Bm[(long long)d*Nc + q0 + q];
    }
    __syncthreads();
    float acc[4][4] = {};
    #pragma unroll
    for (int d=0; d<32; d++) {
        float a[4];
        #pragma unroll
        for (int i=0;i<4;i++) a[i] = At[d][ty*4+i];
        float4 b4 = *(const float4*)&Bt[d][tx*4];
        float bv[4] = {b4.x,b4.y,b4.z,b4.w};
        #pragma unroll
        for (int i=0;i<4;i++)
            #pragma unroll
            for (int j=0;j<4;j++) acc[i][j] = fmaf(a[i], bv[j], acc[i][j]);
    }
    float4 bb = *(const float4*)&bias[q0 + tx*4];
    float bs[4] = {bb.x,bb.y,bb.z,bb.w};
    #pragma unroll
    for (int i=0;i<4;i++) {
        float4 v = make_float4(acc[i][0]+bs[0],acc[i][1]+bs[1],acc[i][2]+bs[2],acc[i][3]+bs[3]);
        *(float4*)&C[(long long)(m0+ty*4+i)*Nc + q0 + tx*4] = v;
    }
}

// ---------------- gcn1: zr = sigmoid(...), emit y=z*de, rg ---------------
__global__ void k_gcn1() {
    __shared__ float us[3][16][68];
    __shared__ float Ws[3][16][128];
    int n0 = blockIdx.x * 64;
    int b  = blockIdx.y;
    int tid = threadIdx.x;
    int tx = tid & 15, ty = tid >> 4;
    const float* deB = g_de + (long long)b*NN*HH;
    const float* p1B = g_p1 + (long long)b*NN*HH;
    const float* p2B = g_p2 + (long long)b*NN*HH;
    const float* WB  = g_W1 + (long long)b*3*65*O1;

    float acc[4][8];
    #pragma unroll
    for (int i=0;i<4;i++)
        #pragma unroll
        for (int j=0;j<8;j++) acc[i][j]=0.f;

    for (int c0=0; c0<64; c0+=16) {
        #pragma unroll
        for (int p=0;p<4;p++) {
            int idx = tid + p*256;
            int cc = idx & 15, i = idx >> 4;
            float d  = deB[(n0+i)*HH + c0+cc];
            float q1 = p1B[(n0+i)*HH + c0+cc];
            float q2 = p2B[(n0+i)*HH + c0+cc];
            us[0][cc][i] = d;
            us[1][cc][i] = q1;
            us[2][cc][i] = 2.f*q2 - d;
        }
        #pragma unroll
        for (int p=0;p<24;p++) {
            int idx = tid + p*256;
            int o = idx & 127, cc = (idx >> 7) & 15, k = idx >> 11;
            Ws[k][cc][o] = WB[(k*65 + c0+cc+1)*O1 + o];
        }
        __syncthreads();
        #pragma unroll
        for (int cc=0; cc<16; cc++)
            #pragma unroll
            for (int k=0;k<3;k++) {
                float a[4];
                #pragma unroll
                for (int i=0;i<4;i++) a[i] = us[k][cc][ty*4+i];
                float4 bA = *(const float4*)&Ws[k][cc][tx*8];
                float4 bB = *(const float4*)&Ws[k][cc][tx*8+4];
                float bv[8] = {bA.x,bA.y,bA.z,bA.w,bB.x,bB.y,bB.z,bB.w};
                #pragma unroll
                for (int i=0;i<4;i++)
                    #pragma unroll
                    for (int j=0;j<8;j++) acc[i][j] = fmaf(a[i], bv[j], acc[i][j]);
            }
        __syncthreads();
    }
    const float* b1B = g_b1 + b*O1;
    int o0 = tx*8;
    #pragma unroll
    for (int i=0;i<4;i++) {
        int n = n0 + ty*4 + i;
        #pragma unroll
        for (int j=0;j<8;j++) {
            int o = o0 + j;
            float v = acc[i][j] + b1B[o];
            float s = 1.f/(1.f + expf(-v));
            if (o < 64)
                g_y[((long long)b*NN + n)*HH + o] = s * deB[n*HH + o];
            else
                g_rg[((long long)b*NN + n)*HH + (o-64)] = s;
        }
    }
}

// -------- gcn2: hc = tanh(...), GRU state, final time projection ---------
__global__ void k_gcn2(const float* __restrict__ ow, const float* __restrict__ ob,
                       float* __restrict__ dout) {
    __shared__ float us[3][16][68];
    __shared__ float Ws[3][16][64];
    __shared__ float st[64][65];
    int n0 = blockIdx.x * 64;
    int b  = blockIdx.y;
    int tid = threadIdx.x;
    int tx = tid & 15, ty = tid >> 4;
    const float* yB  = g_y  + (long long)b*NN*HH;
    const float* p1B = g_p1 + (long long)b*NN*HH;
    const float* p2B = g_p2 + (long long)b*NN*HH;
    const float* WB  = g_W2 + (long long)b*3*65*O2;

    float acc[4][4] = {};
    for (int c0=0; c0<64; c0+=16) {
        #pragma unroll
        for (int p=0;p<4;p++) {
            int idx = tid + p*256;
            int cc = idx & 15, i = idx >> 4;
            float d  = yB [(n0+i)*HH + c0+cc];
            float q1 = p1B[(n0+i)*HH + c0+cc];
            float q2 = p2B[(n0+i)*HH + c0+cc];
            us[0][cc][i] = d;
            us[1][cc][i] = q1;
            us[2][cc][i] = 2.f*q2 - d;
        }
        #pragma unroll
        for (int p=0;p<12;p++) {
            int idx = tid + p*256;
            int o = idx & 63, cc = (idx >> 6) & 15, k = idx >> 10;
            Ws[k][cc][o] = WB[(k*65 + c0+cc+1)*O2 + o];
        }
        __syncthreads();
        #pragma unroll
        for (int cc=0; cc<16; cc++)
            #pragma unroll
            for (int k=0;k<3;k++) {
                float a[4];
                #pragma unroll
                for (int i=0;i<4;i++) a[i] = us[k][cc][ty*4+i];
                float4 b4 = *(const float4*)&Ws[k][cc][tx*4];
                float bv[4] = {b4.x,b4.y,b4.z,b4.w};
                #pragma unroll
                for (int i=0;i<4;i++)
                    #pragma unroll
                    for (int j=0;j<4;j++) acc[i][j] = fmaf(a[i], bv[j], acc[i][j]);
            }
        __syncthreads();
    }
    const float* deB = g_de + (long long)b*NN*HH;
    const float* rgB = g_rg + (long long)b*NN*HH;
    const float* b2B = g_b2 + b*O2;
    #pragma unroll
    for (int i=0;i<4;i++)
        #pragma unroll
        for (int j=0;j<4;j++) {
            int nl = ty*4 + i, o = tx*4 + j;
            int n = n0 + nl;
            float h = tanhf(acc[i][j] + b2B[o]);
            float r = rgB[n*HH + o];
            st[nl][o] = r*deB[n*HH + o] + (1.f - r)*h;
        }
    __syncthreads();
    int t = b % 12, bo = b / 12;
    if (tid < 64) {
        int nl = tid;
        float a = ob[t];
        #pragma unroll
        for (int h=0; h<64; h++) a = fmaf(st[nl][h], ow[t*64+h], a);
        dout[(long long)bo*TT*NN + t*NN + n0 + nl] = a;
    }
}

// -------------------------------------------------------------------------
extern "C" void kernel_launch(void* const* d_in, const int* in_sizes, int n_in,
                              void* d_out, int out_size) {
    const float* hn  = (const float*)d_in[2];
    const float* ne1 = (const float*)d_in[3];
    const float* ne2 = (const float*)d_in[4];
    const float* E   = (const float*)d_in[5];
    const float* Wq  = (const float*)d_in[6];
    const float* bq  = (const float*)d_in[7];
    const float* Wk  = (const float*)d_in[8];
    const float* bk  = (const float*)d_in[9];
    const float* Wv  = (const float*)d_in[10];
    const float* bv  = (const float*)d_in[11];
    const float* taw = (const float*)d_in[12];
    const float* tab = (const float*)d_in[13];
    const float* gwp = (const float*)d_in[14];
    const float* gw  = (const float*)d_in[15];
    const float* gbp = (const float*)d_in[16];
    const float* gb  = (const float*)d_in[17];
    const float* uwp = (const float*)d_in[18];
    const float* uw  = (const float*)d_in[19];
    const float* ubp = (const float*)d_in[20];
    const float* ub  = (const float*)d_in[21];
    const float* ow  = (const float*)d_in[22];
    const float* ob  = (const float*)d_in[23];
    float* out = (float*)d_out;

    k_adj<<<512, 512>>>(E);
    k_attn<<<dim3(NN, BB), 128>>>(hn, ne1, ne2, Wq, bq, Wk, bk, Wv, bv, taw, tab);

    k_wgemm<<<dim3((3*65*O1)/64, BT/64), 256>>>(ne2, gwp, gw, 0);
    k_wgemm<<<dim3((3*65*O2)/64, BT/64), 256>>>(ne2, uwp, uw, 1);
    k_wgemm<<<dim3(O1/64, BT/64), 256>>>(ne2, gbp, gb, 2);
    k_wgemm<<<dim3(O2/64, BT/64), 256>>>(ne2, ubp, ub, 3);

    k_prop<<<dim3(NN/64, BT/2), 256>>>(1);   // p1 = A @ de
    k_prop<<<dim3(NN/64, BT/2), 256>>>(2);   // p2 = A @ p1
    k_gcn1<<<dim3(NN/64, BT), 256>>>();      // -> y, rg

    k_prop<<<dim3(NN/64, BT/2), 256>>>(3);   // p1 = A @ y
    k_prop<<<dim3(NN/64, BT/2), 256>>>(2);   // p2 = A @ p1
    k_gcn2<<<dim3(NN/64, BT), 256>>>(ow, ob, out);
}

// round 3
// speedup vs baseline: 2.1422x; 2.1422x over previous
#include <cuda_runtime.h>
#include <cstdint>
#include <math.h>

#define BB 64
#define TT 12
#define BT 768          // BB*TT
#define NN 512
#define HH 64
#define TDD 32
#define O1 128
#define O2 64
#define PS (NN*HH)      // per-slice elements

// ---------------- scratch (device globals; no allocation) ----------------
__device__ float g_A [NN*NN];                 // adjacency (row-softmax)
__device__ float g_de[BT*NN*HH];              // de_input
__device__ float g_y [BT*NN*HH];              // z * de_input
__device__ float g_rg[BT*NN*HH];              // reset gate
__device__ float g_p1[BT*NN*HH];              // A @ x
__device__ float g_p2[BT*NN*HH];              // A @ (A @ x)
__device__ float g_W1[BT*3*65*O1];            // per-(b,t) gcn1 weights
__device__ float g_W2[BT*3*65*O2];            // per-(b,t) gcn2 weights
__device__ float g_b1[BT*O1];
__device__ float g_b2[BT*O2];

// ---------------- mma.sync tf32 helpers (sm_80+ PTX, valid on compute_103) --
__device__ __forceinline__ uint32_t f2tf32(float f) {
    uint32_t r;
    asm("cvt.rna.tf32.f32 %0, %1;" : "=r"(r) : "f"(f));
    return r;
}
__device__ __forceinline__ void mma_tf32(float* c, const uint32_t* a, const uint32_t* b) {
    asm volatile(
        "mma.sync.aligned.m16n8k8.row.col.f32.tf32.tf32.f32 "
        "{%0,%1,%2,%3}, {%4,%5,%6,%7}, {%8,%9}, {%0,%1,%2,%3};"
        : "+f"(c[0]), "+f"(c[1]), "+f"(c[2]), "+f"(c[3])
        : "r"(a[0]), "r"(a[1]), "r"(a[2]), "r"(a[3]), "r"(b[0]), "r"(b[1]));
}

// ============ tensor-pipe propagation: Y[p][n][c] = sum_m A[n][m] X[p][m][c]
// CTA: 128 A-rows x 64 channels, K=512 in 16 chunks of 32.
// 8 warps (4 row-groups x 2 col-groups), each computes a 32x32 tile.
// mode 1: de->p1   mode 2: p1->p2   mode 3: y->p1
__global__ void __launch_bounds__(256) k_prop_mma(int mode) {
    const float* X; float* Y;
    if (mode == 1)      { X = g_de; Y = g_p1; }
    else if (mode == 2) { X = g_p1; Y = g_p2; }
    else                { X = g_y;  Y = g_p1; }

    __shared__ uint32_t As[128][36];   // A chunk, tf32, pad 36 (conflict-free frags)
    __shared__ uint32_t Xs[32][72];    // X chunk, tf32, pad 72

    int tid = threadIdx.x;
    int wid = tid >> 5, lane = tid & 31;
    int warpR = wid >> 1;              // 0..3
    int warpC = wid & 1;               // 0..1
    int n0 = blockIdx.x * 128;
    const float* Xp = X + (long long)blockIdx.y * PS;
    float*       Yp = Y + (long long)blockIdx.y * PS;

    float acc[2][4][4];
    #pragma unroll
    for (int mm=0;mm<2;mm++)
        #pragma unroll
        for (int nn=0;nn<4;nn++)
            #pragma unroll
            for (int q=0;q<4;q++) acc[mm][nn][q] = 0.f;

    for (int kc = 0; kc < 16; kc++) {
        // A chunk: rows n0..n0+127, k-cols kc*32..+31
        const float* Ab = g_A + (long long)n0 * NN + kc * 32;
        #pragma unroll
        for (int it = 0; it < 4; it++) {
            int idx = tid + it * 256;          // 0..1023 (128 rows x 8 float4)
            int r = idx >> 3, c4 = idx & 7;
            float4 v = *(const float4*)(Ab + (long long)r * NN + c4 * 4);
            uint4 w = make_uint4(f2tf32(v.x), f2tf32(v.y), f2tf32(v.z), f2tf32(v.w));
            *(uint4*)&As[r][c4 * 4] = w;
        }
        // X chunk: k-rows kc*32..+31, 64 channels (already row-major k x c)
        const float* Xb = Xp + kc * 32 * HH;
        #pragma unroll
        for (int it = 0; it < 2; it++) {
            int idx = tid + it * 256;          // 0..511 (32 rows x 16 float4)
            int k = idx >> 4, c4 = idx & 15;
            float4 v = *(const float4*)(Xb + k * HH + c4 * 4);
            uint4 w = make_uint4(f2tf32(v.x), f2tf32(v.y), f2tf32(v.z), f2tf32(v.w));
            *(uint4*)&Xs[k][c4 * 4] = w;
        }
        __syncthreads();

        #pragma unroll
        for (int kk = 0; kk < 4; kk++) {
            uint32_t a[2][4], b[4][2];
            int ar = warpR * 32 + (lane >> 2);
            int ac = kk * 8 + (lane & 3);
            #pragma unroll
            for (int mm = 0; mm < 2; mm++) {
                a[mm][0] = As[ar + mm*16    ][ac];
                a[mm][1] = As[ar + mm*16 + 8][ac];
                a[mm][2] = As[ar + mm*16    ][ac + 4];
                a[mm][3] = As[ar + mm*16 + 8][ac + 4];
            }
            int bk = kk * 8 + (lane & 3);
            int bc = warpC * 32 + (lane >> 2);
            #pragma unroll
            for (int nn = 0; nn < 4; nn++) {
                b[nn][0] = Xs[bk    ][bc + nn*8];
                b[nn][1] = Xs[bk + 4][bc + nn*8];
            }
            #pragma unroll
            for (int mm = 0; mm < 2; mm++)
                #pragma unroll
                for (int nn = 0; nn < 4; nn++)
                    mma_tf32(acc[mm][nn], a[mm], b[nn]);
        }
        __syncthreads();
    }

    // epilogue: fragment layout -> Y[n][c]
    int r0 = n0 + warpR * 32 + (lane >> 2);
    int c0 = warpC * 32 + 2 * (lane & 3);
    #pragma unroll
    for (int mm = 0; mm < 2; mm++)
        #pragma unroll
        for (int nn = 0; nn < 4; nn++) {
            float* d0 = Yp + (long long)(r0 + mm*16) * HH + c0 + nn*8;
            *(float2*)d0 = make_float2(acc[mm][nn][0], acc[mm][nn][1]);
            float* d1 = Yp + (long long)(r0 + mm*16 + 8) * HH + c0 + nn*8;
            *(float2*)d1 = make_float2(acc[mm][nn][2], acc[mm][nn][3]);
        }
}

// ---------------- adjacency: A = softmax_row(relu(E E^T)) ----------------
__global__ void k_adj(const float* __restrict__ E) {
    int n = blockIdx.x;
    int m = threadIdx.x;               // 512 threads
    __shared__ float en[16];
    __shared__ float red[512];
    if (m < 16) en[m] = E[n*16 + m];
    __syncthreads();
    float s = 0.f;
    #pragma unroll
    for (int j = 0; j < 16; j++) s = fmaf(en[j], E[m*16 + j], s);
    s = fmaxf(s, 0.f);
    red[m] = s; __syncthreads();
    for (int off = 256; off > 0; off >>= 1) {
        if (m < off) red[m] = fmaxf(red[m], red[m+off]);
        __syncthreads();
    }
    float mx = red[0]; __syncthreads();
    float e = expf(s - mx);
    red[m] = e; __syncthreads();
    for (int off = 256; off > 0; off >>= 1) {
        if (m < off) red[m] += red[m+off];
        __syncthreads();
    }
    g_A[n*NN + m] = e / red[0];
}

// ---------------- temporal attention -> de_input -------------------------
__global__ void k_attn(const float* __restrict__ hn, const float* __restrict__ ne1,
                       const float* __restrict__ ne2,
                       const float* __restrict__ Wq, const float* __restrict__ bq,
                       const float* __restrict__ Wk, const float* __restrict__ bk,
                       const float* __restrict__ Wv, const float* __restrict__ bv,
                       const float* __restrict__ taw, const float* __restrict__ tab) {
    int n = blockIdx.x, b = blockIdx.y;
    int tid = threadIdx.x;     // 128
    __shared__ float xs[64], sp[32], sq[TT*TDD], ks[64], vs[64], qs[TT*64], lg[96];

    if (tid < 64)            xs[tid]    = hn[((long long)b*NN + n)*HH + tid];
    else if (tid < 96)       sp[tid-64] = ne1[b*TT*TDD + 11*TDD + (tid-64)];
    for (int i = tid; i < TT*TDD; i += 128) sq[i] = ne2[b*TT*TDD + i];
    __syncthreads();

    {
        int h = tid & 63;
        const float* W  = (tid < 64) ? Wk : Wv;
        const float* bb = (tid < 64) ? bk : bv;
        float a = bb[h];
        #pragma unroll
        for (int j=0;j<32;j++) a = fmaf(sp[j], W[j*64+h], a);
        #pragma unroll
        for (int j=0;j<64;j++) a = fmaf(xs[j], W[(32+j)*64+h], a);
        a = fmaxf(a, 0.f);
        if (tid < 64) ks[h] = a; else vs[h] = a;
    }
    for (int idx = tid; idx < TT*64; idx += 128) {
        int t = idx >> 6, h = idx & 63;
        float a = bq[h];
        #pragma unroll
        for (int j=0;j<32;j++) a = fmaf(sq[t*32+j], Wq[j*64+h], a);
        #pragma unroll
        for (int j=0;j<64;j++) a = fmaf(xs[j], Wq[(32+j)*64+h], a);
        qs[idx] = fmaxf(a, 0.f);
    }
    __syncthreads();
    if (tid < 96) {
        int d = tid / 12, t = tid % 12;
        float a = 0.f;
        #pragma unroll
        for (int c=0;c<8;c++) a = fmaf(qs[t*64 + d*8 + c], ks[d*8+c], a);
        lg[d*12+t] = a;
    }
    __syncthreads();
    if (tid < 8) {
        int d = tid;
        float mx = -1e30f;
        for (int t=0;t<12;t++) mx = fmaxf(mx, lg[d*12+t]);
        float s = 0.f;
        for (int t=0;t<12;t++){ float e = expf(lg[d*12+t]-mx); lg[d*12+t]=e; s+=e; }
        float inv = 1.f/s;
        for (int t=0;t<12;t++) lg[d*12+t] *= inv;
    }
    __syncthreads();
    for (int idx = tid; idx < TT*64; idx += 128) {
        int t = idx >> 6, h = idx & 63;
        float a = tab[h];
        #pragma unroll
        for (int i=0;i<64;i++) {
            a = fmaf(xs[i], taw[i*64 + h], a);
            float o = lg[(i>>3)*12 + t] * vs[i];
            a = fmaf(o, taw[4096 + i*64 + h], a);
        }
        g_de[((long long)(b*12+t)*NN + n)*HH + h] = a;
    }
}

// ---------------- per-(b,t) weights: C[768][Nc] = temb@B + bias ----------
__global__ void k_wgemm(const float* __restrict__ Am, const float* __restrict__ Bm,
                        const float* __restrict__ bias, int mode) {
    float* C; int Nc;
    if (mode == 0)      { C = g_W1; Nc = 3*65*O1; }
    else if (mode == 1) { C = g_W2; Nc = 3*65*O2; }
    else if (mode == 2) { C = g_b1; Nc = O1; }
    else                { C = g_b2; Nc = O2; }

    __shared__ float At[32][65];
    __shared__ float Bt[32][64];
    int q0 = blockIdx.x * 64;
    int m0 = blockIdx.y * 64;
    int tid = threadIdx.x;
    int tx = tid & 15, ty = tid >> 4;
    #pragma unroll
    for (int p=0;p<8;p++) {
        int idx = tid + p*256;
        int d = idx & 31, m = idx >> 5;
        At[d][m] = Am[(m0+m)*32 + d];
    }
    #pragma unroll
    for (int p=0;p<8;p++) {
        int idx = tid + p*256;
        int q = idx & 63, d = idx >> 6;
        Bt[d][q] = Bm[(long long)d*Nc + q0 + q];
    }
    __syncthreads();
    float acc[4][4] = {};
    #pragma unroll
    for (int d=0; d<32; d++) {
        float a[4];
        #pragma unroll
        for (int i=0;i<4;i++) a[i] = At[d][ty*4+i];
        float4 b4 = *(const float4*)&Bt[d][tx*4];
        float bv[4] = {b4.x,b4.y,b4.z,b4.w};
        #pragma unroll
        for (int i=0;i<4;i++)
            #pragma unroll
            for (int j=0;j<4;j++) acc[i][j] = fmaf(a[i], bv[j], acc[i][j]);
    }
    float4 bb = *(const float4*)&bias[q0 + tx*4];
    float bs[4] = {bb.x,bb.y,bb.z,bb.w};
    #pragma unroll
    for (int i=0;i<4;i++) {
        float4 v = make_float4(acc[i][0]+bs[0],acc[i][1]+bs[1],acc[i][2]+bs[2],acc[i][3]+bs[3]);
        *(float4*)&C[(long long)(m0+ty*4+i)*Nc + q0 + tx*4] = v;
    }
}

// ---------------- gcn1: zr = sigmoid(...), emit y=z*de, rg ---------------
__global__ void k_gcn1() {
    __shared__ float us[3][16][68];
    __shared__ float Ws[3][16][128];
    int n0 = blockIdx.x * 64;
    int b  = blockIdx.y;
    int tid = threadIdx.x;
    int tx = tid & 15, ty = tid >> 4;
    const float* deB = g_de + (long long)b*NN*HH;
    const float* p1B = g_p1 + (long long)b*NN*HH;
    const float* p2B = g_p2 + (long long)b*NN*HH;
    const float* WB  = g_W1 + (long long)b*3*65*O1;

    float acc[4][8];
    #pragma unroll
    for (int i=0;i<4;i++)
        #pragma unroll
        for (int j=0;j<8;j++) acc[i][j]=0.f;

    for (int c0=0; c0<64; c0+=16) {
        #pragma unroll
        for (int p=0;p<4;p++) {
            int idx = tid + p*256;
            int cc = idx & 15, i = idx >> 4;
            float d  = deB[(n0+i)*HH + c0+cc];
            float q1 = p1B[(n0+i)*HH + c0+cc];
            float q2 = p2B[(n0+i)*HH + c0+cc];
            us[0][cc][i] = d;
            us[1][cc][i] = q1;
            us[2][cc][i] = 2.f*q2 - d;
        }
        #pragma unroll
        for (int p=0;p<24;p++) {
            int idx = tid + p*256;
            int o = idx & 127, cc = (idx >> 7) & 15, k = idx >> 11;
            Ws[k][cc][o] = WB[(k*65 + c0+cc+1)*O1 + o];
        }
        __syncthreads();
        #pragma unroll
        for (int cc=0; cc<16; cc++)
            #pragma unroll
            for (int k=0;k<3;k++) {
                float a[4];
                #pragma unroll
                for (int i=0;i<4;i++) a[i] = us[k][cc][ty*4+i];
                float4 bA = *(const float4*)&Ws[k][cc][tx*8];
                float4 bB = *(const float4*)&Ws[k][cc][tx*8+4];
                float bv[8] = {bA.x,bA.y,bA.z,bA.w,bB.x,bB.y,bB.z,bB.w};
                #pragma unroll
                for (int i=0;i<4;i++)
                    #pragma unroll
                    for (int j=0;j<8;j++) acc[i][j] = fmaf(a[i], bv[j], acc[i][j]);
            }
        __syncthreads();
    }
    const float* b1B = g_b1 + b*O1;
    int o0 = tx*8;
    #pragma unroll
    for (int i=0;i<4;i++) {
        int n = n0 + ty*4 + i;
        #pragma unroll
        for (int j=0;j<8;j++) {
            int o = o0 + j;
            float v = acc[i][j] + b1B[o];
            float s = 1.f/(1.f + expf(-v));
            if (o < 64)
                g_y[((long long)b*NN + n)*HH + o] = s * deB[n*HH + o];
            else
                g_rg[((long long)b*NN + n)*HH + (o-64)] = s;
        }
    }
}

// -------- gcn2: hc = tanh(...), GRU state, final time projection ---------
__global__ void k_gcn2(const float* __restrict__ ow, const float* __restrict__ ob,
                       float* __restrict__ dout) {
    __shared__ float us[3][16][68];
    __shared__ float Ws[3][16][64];
    __shared__ float st[64][65];
    int n0 = blockIdx.x * 64;
    int b  = blockIdx.y;
    int tid = threadIdx.x;
    int tx = tid & 15, ty = tid >> 4;
    const float* yB  = g_y  + (long long)b*NN*HH;
    const float* p1B = g_p1 + (long long)b*NN*HH;
    const float* p2B = g_p2 + (long long)b*NN*HH;
    const float* WB  = g_W2 + (long long)b*3*65*O2;

    float acc[4][4] = {};
    for (int c0=0; c0<64; c0+=16) {
        #pragma unroll
        for (int p=0;p<4;p++) {
            int idx = tid + p*256;
            int cc = idx & 15, i = idx >> 4;
            float d  = yB [(n0+i)*HH + c0+cc];
            float q1 = p1B[(n0+i)*HH + c0+cc];
            float q2 = p2B[(n0+i)*HH + c0+cc];
            us[0][cc][i] = d;
            us[1][cc][i] = q1;
            us[2][cc][i] = 2.f*q2 - d;
        }
        #pragma unroll
        for (int p=0;p<12;p++) {
            int idx = tid + p*256;
            int o = idx & 63, cc = (idx >> 6) & 15, k = idx >> 10;
            Ws[k][cc][o] = WB[(k*65 + c0+cc+1)*O2 + o];
        }
        __syncthreads();
        #pragma unroll
        for (int cc=0; cc<16; cc++)
            #pragma unroll
            for (int k=0;k<3;k++) {
                float a[4];
                #pragma unroll
                for (int i=0;i<4;i++) a[i] = us[k][cc][ty*4+i];
                float4 b4 = *(const float4*)&Ws[k][cc][tx*4];
                float bv[4] = {b4.x,b4.y,b4.z,b4.w};
                #pragma unroll
                for (int i=0;i<4;i++)
                    #pragma unroll
                    for (int j=0;j<4;j++) acc[i][j] = fmaf(a[i], bv[j], acc[i][j]);
            }
        __syncthreads();
    }
    const float* deB = g_de + (long long)b*NN*HH;
    const float* rgB = g_rg + (long long)b*NN*HH;
    const float* b2B = g_b2 + b*O2;
    #pragma unroll
    for (int i=0;i<4;i++)
        #pragma unroll
        for (int j=0;j<4;j++) {
            int nl = ty*4 + i, o = tx*4 + j;
            int n = n0 + nl;
            float h = tanhf(acc[i][j] + b2B[o]);
            float r = rgB[n*HH + o];
            st[nl][o] = r*deB[n*HH + o] + (1.f - r)*h;
        }
    __syncthreads();
    int t = b % 12, bo = b / 12;
    if (tid < 64) {
        int nl = tid;
        float a = ob[t];
        #pragma unroll
        for (int h=0; h<64; h++) a = fmaf(st[nl][h], ow[t*64+h], a);
        dout[(long long)bo*TT*NN + t*NN + n0 + nl] = a;
    }
}

// -------------------------------------------------------------------------
extern "C" void kernel_launch(void* const* d_in, const int* in_sizes, int n_in,
                              void* d_out, int out_size) {
    const float* hn  = (const float*)d_in[2];
    const float* ne1 = (const float*)d_in[3];
    const float* ne2 = (const float*)d_in[4];
    const float* E   = (const float*)d_in[5];
    const float* Wq  = (const float*)d_in[6];
    const float* bq  = (const float*)d_in[7];
    const float* Wk  = (const float*)d_in[8];
    const float* bk  = (const float*)d_in[9];
    const float* Wv  = (const float*)d_in[10];
    const float* bv  = (const float*)d_in[11];
    const float* taw = (const float*)d_in[12];
    const float* tab = (const float*)d_in[13];
    const float* gwp = (const float*)d_in[14];
    const float* gw  = (const float*)d_in[15];
    const float* gbp = (const float*)d_in[16];
    const float* gb  = (const float*)d_in[17];
    const float* uwp = (const float*)d_in[18];
    const float* uw  = (const float*)d_in[19];
    const float* ubp = (const float*)d_in[20];
    const float* ub  = (const float*)d_in[21];
    const float* ow  = (const float*)d_in[22];
    const float* ob  = (const float*)d_in[23];
    float* out = (float*)d_out;

    dim3 gprop(NN/128, BT);    // (4, 768)

    k_adj<<<512, 512>>>(E);
    k_attn<<<dim3(NN, BB), 128>>>(hn, ne1, ne2, Wq, bq, Wk, bk, Wv, bv, taw, tab);

    k_wgemm<<<dim3((3*65*O1)/64, BT/64), 256>>>(ne2, gwp, gw, 0);
    k_wgemm<<<dim3((3*65*O2)/64, BT/64), 256>>>(ne2, uwp, uw, 1);
    k_wgemm<<<dim3(O1/64, BT/64), 256>>>(ne2, gbp, gb, 2);
    k_wgemm<<<dim3(O2/64, BT/64), 256>>>(ne2, ubp, ub, 3);

    k_prop_mma<<<gprop, 256>>>(1);   // p1 = A @ de
    k_prop_mma<<<gprop, 256>>>(2);   // p2 = A @ p1
    k_gcn1<<<dim3(NN/64, BT), 256>>>();      // -> y, rg

    k_prop_mma<<<gprop, 256>>>(3);   // p1 = A @ y
    k_prop_mma<<<gprop, 256>>>(2);   // p2 = A @ p1
    k_gcn2<<<dim3(NN/64, BT), 256>>>(ow, ob, out);
}

// round 5
// speedup vs baseline: 3.3663x; 1.5714x over previous
#include <cuda_runtime.h>
#include <cstdint>
#include <math.h>

#define BB 64
#define TT 12
#define BT 768          // BB*TT
#define NN 512
#define HH 64
#define TDD 32
#define O1 128
#define O2 64
#define PS (NN*HH)      // per-slice elements

// ---------------- scratch (device globals; no allocation) ----------------
__device__ float g_A [NN*NN];                 // adjacency (row-softmax)
__device__ float g_de[BT*NN*HH];              // de_input
__device__ float g_y [BT*NN*HH];              // z * de_input
__device__ float g_rg[BT*NN*HH];              // reset gate
__device__ float g_p1[BT*NN*HH];              // A @ x
__device__ float g_p2[BT*NN*HH];              // s2 = 2*A@(A@x) - x  (fused)
__device__ float g_W1[BT*3*65*O1];            // per-(b,t) gcn1 weights
__device__ float g_W2[BT*3*65*O2];            // per-(b,t) gcn2 weights
__device__ float g_b1[BT*O1];
__device__ float g_b2[BT*O2];
__device__ float g_spk[BB*64];                // per-b  k head bias part
__device__ float g_spv[BB*64];                // per-b  v head bias part
__device__ float g_sqq[BB*TT*64];             // per-(b,t) q bias part

// ---------------- mma.sync tf32 helpers ----------------------------------
__device__ __forceinline__ uint32_t f2tf32(float f) {
    uint32_t r;
    asm("cvt.rna.tf32.f32 %0, %1;" : "=r"(r) : "f"(f));
    return r;
}
__device__ __forceinline__ void mma_tf32(float* c, const uint32_t* a, const uint32_t* b) {
    asm volatile(
        "mma.sync.aligned.m16n8k8.row.col.f32.tf32.tf32.f32 "
        "{%0,%1,%2,%3}, {%4,%5,%6,%7}, {%8,%9}, {%0,%1,%2,%3};"
        : "+f"(c[0]), "+f"(c[1]), "+f"(c[2]), "+f"(c[3])
        : "r"(a[0]), "r"(a[1]), "r"(a[2]), "r"(a[3]), "r"(b[0]), "r"(b[1]));
}

// ============ tensor-pipe propagation: Y[p][n][c] = sum_m A[n][m] X[p][m][c]
// mode 1: de->p1   mode 2: p2 = 2*(A@p1) - de   mode 3: y->p1   mode 4: p2 = 2*(A@p1) - y
__global__ void __launch_bounds__(256) k_prop_mma(int mode) {
    const float* X; float* Y;
    if (mode == 1)      { X = g_de; Y = g_p1; }
    else if (mode == 3) { X = g_y;  Y = g_p1; }
    else                { X = g_p1; Y = g_p2; }
    const bool s2m = (mode == 2) || (mode == 4);
    const float* X0 = (mode == 2) ? g_de : g_y;   // only used when s2m

    __shared__ uint32_t As[128][36];
    __shared__ uint32_t Xs[32][72];

    int tid = threadIdx.x;
    int wid = tid >> 5, lane = tid & 31;
    int warpR = wid >> 1;              // 0..3
    int warpC = wid & 1;               // 0..1
    int n0 = blockIdx.x * 128;
    const float* Xp  = X  + (long long)blockIdx.y * PS;
    const float* X0p = X0 + (long long)blockIdx.y * PS;
    float*       Yp  = Y  + (long long)blockIdx.y * PS;

    float acc[2][4][4];
    #pragma unroll
    for (int mm=0;mm<2;mm++)
        #pragma unroll
        for (int nn=0;nn<4;nn++)
            #pragma unroll
            for (int q=0;q<4;q++) acc[mm][nn][q] = 0.f;

    for (int kc = 0; kc < 16; kc++) {
        const float* Ab = g_A + (long long)n0 * NN + kc * 32;
        #pragma unroll
        for (int it = 0; it < 4; it++) {
            int idx = tid + it * 256;          // 128 rows x 8 float4
            int r = idx >> 3, c4 = idx & 7;
            float4 v = *(const float4*)(Ab + (long long)r * NN + c4 * 4);
            uint4 w = make_uint4(f2tf32(v.x), f2tf32(v.y), f2tf32(v.z), f2tf32(v.w));
            *(uint4*)&As[r][c4 * 4] = w;
        }
        const float* Xb = Xp + kc * 32 * HH;
        #pragma unroll
        for (int it = 0; it < 2; it++) {
            int idx = tid + it * 256;          // 32 rows x 16 float4
            int k = idx >> 4, c4 = idx & 15;
            float4 v = *(const float4*)(Xb + k * HH + c4 * 4);
            uint4 w = make_uint4(f2tf32(v.x), f2tf32(v.y), f2tf32(v.z), f2tf32(v.w));
            *(uint4*)&Xs[k][c4 * 4] = w;
        }
        __syncthreads();

        #pragma unroll
        for (int kk = 0; kk < 4; kk++) {
            uint32_t a[2][4], b[4][2];
            int ar = warpR * 32 + (lane >> 2);
            int ac = kk * 8 + (lane & 3);
            #pragma unroll
            for (int mm = 0; mm < 2; mm++) {
                a[mm][0] = As[ar + mm*16    ][ac];
                a[mm][1] = As[ar + mm*16 + 8][ac];
                a[mm][2] = As[ar + mm*16    ][ac + 4];
                a[mm][3] = As[ar + mm*16 + 8][ac + 4];
            }
            int bk = kk * 8 + (lane & 3);
            int bc = warpC * 32 + (lane >> 2);
            #pragma unroll
            for (int nn = 0; nn < 4; nn++) {
                b[nn][0] = Xs[bk    ][bc + nn*8];
                b[nn][1] = Xs[bk + 4][bc + nn*8];
            }
            #pragma unroll
            for (int mm = 0; mm < 2; mm++)
                #pragma unroll
                for (int nn = 0; nn < 4; nn++)
                    mma_tf32(acc[mm][nn], a[mm], b[nn]);
        }
        __syncthreads();
    }

    int r0 = n0 + warpR * 32 + (lane >> 2);
    int c0 = warpC * 32 + 2 * (lane & 3);
    #pragma unroll
    for (int mm = 0; mm < 2; mm++)
        #pragma unroll
        for (int nn = 0; nn < 4; nn++) {
            int r = r0 + mm*16, c = c0 + nn*8;
            float2 v0 = make_float2(acc[mm][nn][0], acc[mm][nn][1]);
            float2 v1 = make_float2(acc[mm][nn][2], acc[mm][nn][3]);
            if (s2m) {
                float2 x0a = *(const float2*)(X0p + (long long)r * HH + c);
                float2 x0b = *(const float2*)(X0p + (long long)(r+8) * HH + c);
                v0 = make_float2(2.f*v0.x - x0a.x, 2.f*v0.y - x0a.y);
                v1 = make_float2(2.f*v1.x - x0b.x, 2.f*v1.y - x0b.y);
            }
            *(float2*)(Yp + (long long)r * HH + c)     = v0;
            *(float2*)(Yp + (long long)(r+8) * HH + c) = v1;
        }
}

// ---------------- adjacency: A = softmax_row(relu(E E^T)) ----------------
__global__ void k_adj(const float* __restrict__ E) {
    int n = blockIdx.x;
    int m = threadIdx.x;               // 512 threads
    __shared__ float en[16];
    __shared__ float red[512];
    if (m < 16) en[m] = E[n*16 + m];
    __syncthreads();
    float s = 0.f;
    #pragma unroll
    for (int j = 0; j < 16; j++) s = fmaf(en[j], E[m*16 + j], s);
    s = fmaxf(s, 0.f);
    red[m] = s; __syncthreads();
    for (int off = 256; off > 0; off >>= 1) {
        if (m < off) red[m] = fmaxf(red[m], red[m+off]);
        __syncthreads();
    }
    float mx = red[0]; __syncthreads();
    float e = expf(s - mx);
    red[m] = e; __syncthreads();
    for (int off = 256; off > 0; off >>= 1) {
        if (m < off) red[m] += red[m+off];
        __syncthreads();
    }
    g_A[n*NN + m] = e / red[0];
}

// ---------------- attention prelude: per-b / per-(b,t) bias parts --------
__global__ void k_attn_pre(const float* __restrict__ ne1, const float* __restrict__ ne2,
                           const float* __restrict__ Wq, const float* __restrict__ bq,
                           const float* __restrict__ Wk, const float* __restrict__ bk,
                           const float* __restrict__ Wv, const float* __restrict__ bv) {
    int b = blockIdx.x;
    int h = threadIdx.x;               // 64 threads
    __shared__ float sp[32], sq[TT*TDD];
    if (h < 32) sp[h] = ne1[b*TT*TDD + 11*TDD + h];
    for (int i = h; i < TT*TDD; i += 64) sq[i] = ne2[b*TT*TDD + i];
    __syncthreads();
    float ak = bk[h], av = bv[h];
    #pragma unroll
    for (int j = 0; j < 32; j++) {
        ak = fmaf(sp[j], Wk[j*64+h], ak);
        av = fmaf(sp[j], Wv[j*64+h], av);
    }
    g_spk[b*64+h] = ak;
    g_spv[b*64+h] = av;
    #pragma unroll
    for (int t = 0; t < TT; t++) {
        float a = bq[h];
        #pragma unroll
        for (int j = 0; j < 32; j++) a = fmaf(sq[t*32+j], Wq[j*64+h], a);
        g_sqq[(b*TT+t)*64+h] = a;
    }
}

// ---------------- temporal attention main (hoisted) -> de_input ----------
__global__ void k_attn2(const float* __restrict__ hn,
                        const float* __restrict__ Wq, const float* __restrict__ Wk,
                        const float* __restrict__ Wv,
                        const float* __restrict__ taw, const float* __restrict__ tab) {
    int n = blockIdx.x, b = blockIdx.y;
    int tid = threadIdx.x;             // 128
    __shared__ float xs[64], ks[64], vs[64], xq[64], t1[64], lg[96], vw[TT*64], sqs[TT*64];

    if (tid < 64) xs[tid] = hn[((long long)b*NN + n)*HH + tid];
    for (int i = tid; i < TT*64; i += 128) sqs[i] = g_sqq[b*TT*64 + i];
    __syncthreads();

    {   // four 64x64 GEMVs, split across two thread-halves
        int h = tid & 63;
        if (tid < 64) {
            float a = g_spk[b*64+h], a2 = 0.f;
            #pragma unroll
            for (int j = 0; j < 64; j++) {
                a  = fmaf(xs[j], Wk[(32+j)*64+h], a);
                a2 = fmaf(xs[j], Wq[(32+j)*64+h], a2);
            }
            ks[h] = fmaxf(a, 0.f);
            xq[h] = a2;
        } else {
            float a = g_spv[b*64+h], a2 = tab[h];
            #pragma unroll
            for (int j = 0; j < 64; j++) {
                a  = fmaf(xs[j], Wv[(32+j)*64+h], a);
                a2 = fmaf(xs[j], taw[j*64+h], a2);
            }
            vs[h] = fmaxf(a, 0.f);
            t1[h] = a2;
        }
    }
    __syncthreads();
    if (tid < 96) {                    // logits per (head d, time t)
        int d = tid / 12, t = tid % 12;
        float a = 0.f;
        #pragma unroll
        for (int c = 0; c < 8; c++) {
            int h = d*8 + c;
            float q = fmaxf(xq[h] + sqs[t*64+h], 0.f);
            a = fmaf(q, ks[h], a);
        }
        lg[d*12+t] = a;
    }
    __syncthreads();
    if (tid < 8) {                     // softmax over t within each head
        int d = tid;
        float mx = -1e30f;
        for (int t = 0; t < 12; t++) mx = fmaxf(mx, lg[d*12+t]);
        float s = 0.f;
        for (int t = 0; t < 12; t++) { float e = expf(lg[d*12+t]-mx); lg[d*12+t] = e; s += e; }
        float inv = 1.f/s;
        for (int t = 0; t < 12; t++) lg[d*12+t] *= inv;
    }
    __syncthreads();
    for (int idx = tid; idx < TT*64; idx += 128) {
        int t = idx >> 6, i = idx & 63;
        vw[idx] = lg[(i>>3)*12 + t] * vs[i];
    }
    __syncthreads();
    for (int idx = tid; idx < TT*64; idx += 128) {
        int t = idx >> 6, h = idx & 63;
        float a = t1[h];
        #pragma unroll
        for (int i = 0; i < 64; i++) a = fmaf(vw[t*64+i], taw[4096 + i*64 + h], a);
        g_de[((long long)(b*12+t)*NN + n)*HH + h] = a;
    }
}

// ---------------- per-(b,t) weights: C[768][Nc] = temb@B + bias ----------
__global__ void k_wgemm(const float* __restrict__ Am, const float* __restrict__ Bm,
                        const float* __restrict__ bias, int mode) {
    float* C; int Nc;
    if (mode == 0)      { C = g_W1; Nc = 3*65*O1; }
    else if (mode == 1) { C = g_W2; Nc = 3*65*O2; }
    else if (mode == 2) { C = g_b1; Nc = O1; }
    else                { C = g_b2; Nc = O2; }

    __shared__ float At[32][65];
    __shared__ float Bt[32][64];
    int q0 = blockIdx.x * 64;
    int m0 = blockIdx.y * 64;
    int tid = threadIdx.x;
    int tx = tid & 15, ty = tid >> 4;
    #pragma unroll
    for (int p=0;p<8;p++) {
        int idx = tid + p*256;
        int d = idx & 31, m = idx >> 5;
        At[d][m] = Am[(m0+m)*32 + d];
    }
    #pragma unroll
    for (int p=0;p<8;p++) {
        int idx = tid + p*256;
        int q = idx & 63, d = idx >> 6;
        Bt[d][q] = Bm[(long long)d*Nc + q0 + q];
    }
    __syncthreads();
    float acc[4][4] = {};
    #pragma unroll
    for (int d=0; d<32; d++) {
        float a[4];
        #pragma unroll
        for (int i=0;i<4;i++) a[i] = At[d][ty*4+i];
        float4 b4 = *(const float4*)&Bt[d][tx*4];
        float bv[4] = {b4.x,b4.y,b4.z,b4.w};
        #pragma unroll
        for (int i=0;i<4;i++)
            #pragma unroll
            for (int j=0;j<4;j++) acc[i][j] = fmaf(a[i], bv[j], acc[i][j]);
    }
    float4 bb = *(const float4*)&bias[q0 + tx*4];
    float bs[4] = {bb.x,bb.y,bb.z,bb.w};
    #pragma unroll
    for (int i=0;i<4;i++) {
        float4 v = make_float4(acc[i][0]+bs[0],acc[i][1]+bs[1],acc[i][2]+bs[2],acc[i][3]+bs[3]);
        *(float4*)&C[(long long)(m0+ty*4+i)*Nc + q0 + tx*4] = v;
    }
}

// ======== gcn1 via mma: zr = sigmoid(xg @ W1 + b1) -> y = z*de, rg ========
// CTA: 128 nodes x 128 outs, K=192 (3 x 64 channels) in 6 chunks of 32.
// 8 warps: 4 row-groups x 2 col-groups; warp tile 32x64.
__global__ void __launch_bounds__(256) k_gcn1_mma() {
    __shared__ uint32_t As[128][36];
    __shared__ uint32_t Ws[32][132];
    int tid = threadIdx.x;
    int wid = tid >> 5, lane = tid & 31;
    int warpR = wid >> 1, warpC = wid & 1;
    int n0 = blockIdx.x * 128;
    int b  = blockIdx.y;
    const float* srcs[3] = { g_de + (long long)b*PS, g_p1 + (long long)b*PS, g_p2 + (long long)b*PS };
    const float* WB = g_W1 + (long long)b*3*65*O1;

    float acc[2][8][4];
    #pragma unroll
    for (int mm=0;mm<2;mm++)
        #pragma unroll
        for (int nn=0;nn<8;nn++)
            #pragma unroll
            for (int q=0;q<4;q++) acc[mm][nn][q] = 0.f;

    for (int kc = 0; kc < 6; kc++) {
        int k = kc >> 1, c0 = (kc & 1) * 32;
        const float* S = srcs[k];
        #pragma unroll
        for (int it = 0; it < 4; it++) {       // A: 128 rows x 8 float4
            int idx = tid + it * 256;
            int r = idx >> 3, f4 = idx & 7;
            float4 v = *(const float4*)(S + (long long)(n0+r)*HH + c0 + f4*4);
            uint4 w = make_uint4(f2tf32(v.x), f2tf32(v.y), f2tf32(v.z), f2tf32(v.w));
            *(uint4*)&As[r][f4*4] = w;
        }
        #pragma unroll
        for (int it = 0; it < 4; it++) {       // W: 32 rows x 32 float4
            int idx = tid + it * 256;
            int j = idx >> 5, f4 = idx & 31;
            float4 v = *(const float4*)(WB + (long long)(k*65 + 1 + c0 + j)*O1 + f4*4);
            uint4 w = make_uint4(f2tf32(v.x), f2tf32(v.y), f2tf32(v.z), f2tf32(v.w));
            *(uint4*)&Ws[j][f4*4] = w;
        }
        __syncthreads();
        #pragma unroll
        for (int kk = 0; kk < 4; kk++) {
            uint32_t a[2][4], bfr[8][2];
            int ar = warpR * 32 + (lane >> 2);
            int ac = kk * 8 + (lane & 3);
            #pragma unroll
            for (int mm = 0; mm < 2; mm++) {
                a[mm][0] = As[ar + mm*16    ][ac];
                a[mm][1] = As[ar + mm*16 + 8][ac];
                a[mm][2] = As[ar + mm*16    ][ac + 4];
                a[mm][3] = As[ar + mm*16 + 8][ac + 4];
            }
            int bk = kk * 8 + (lane & 3);
            int bc = warpC * 64 + (lane >> 2);
            #pragma unroll
            for (int nn = 0; nn < 8; nn++) {
                bfr[nn][0] = Ws[bk    ][bc + nn*8];
                bfr[nn][1] = Ws[bk + 4][bc + nn*8];
            }
            #pragma unroll
            for (int mm = 0; mm < 2; mm++)
                #pragma unroll
                for (int nn = 0; nn < 8; nn++)
                    mma_tf32(acc[mm][nn], a[mm], bfr[nn]);
        }
        __syncthreads();
    }

    const float* b1B = g_b1 + b*O1;
    const float* deB = g_de + (long long)b*PS;
    float* yB  = g_y  + (long long)b*PS;
    float* rgB = g_rg + (long long)b*PS;
    int r0 = n0 + warpR * 32 + (lane >> 2);
    int co = warpC * 64 + 2 * (lane & 3);
    #pragma unroll
    for (int mm = 0; mm < 2; mm++)
        #pragma unroll
        for (int nn = 0; nn < 8; nn++) {
            int o = co + nn*8;
            float bb0 = b1B[o], bb1 = b1B[o+1];
            #pragma unroll
            for (int half = 0; half < 2; half++) {
                int r = r0 + mm*16 + half*8;
                float s0 = 1.f/(1.f + expf(-(acc[mm][nn][half*2+0] + bb0)));
                float s1 = 1.f/(1.f + expf(-(acc[mm][nn][half*2+1] + bb1)));
                if (warpC == 0) {      // o in [0,64): z -> y = z*de
                    float2 d = *(const float2*)(deB + (long long)r*HH + o);
                    *(float2*)(yB + (long long)r*HH + o) = make_float2(s0*d.x, s1*d.y);
                } else {               // o in [64,128): rg
                    *(float2*)(rgB + (long long)r*HH + (o-64)) = make_float2(s0, s1);
                }
            }
        }
}

// ======== gcn2 via mma: hc = tanh(.), GRU state, final time projection ====
// CTA: 128 nodes x 64 outs, K=192 in 6 chunks. 8 warps 4x2, warp tile 32x32.
__global__ void __launch_bounds__(256) k_gcn2_mma(const float* __restrict__ ow,
                                                  const float* __restrict__ ob,
                                                  float* __restrict__ dout) {
    __shared__ union {
        struct { uint32_t As[128][36]; uint32_t Ws[32][68]; } ld;
        float st[128][65];
    } sm;
    int tid = threadIdx.x;
    int wid = tid >> 5, lane = tid & 31;
    int warpR = wid >> 1, warpC = wid & 1;
    int n0 = blockIdx.x * 128;
    int b  = blockIdx.y;
    const float* srcs[3] = { g_y + (long long)b*PS, g_p1 + (long long)b*PS, g_p2 + (long long)b*PS };
    const float* WB = g_W2 + (long long)b*3*65*O2;

    float acc[2][4][4];
    #pragma unroll
    for (int mm=0;mm<2;mm++)
        #pragma unroll
        for (int nn=0;nn<4;nn++)
            #pragma unroll
            for (int q=0;q<4;q++) acc[mm][nn][q] = 0.f;

    for (int kc = 0; kc < 6; kc++) {
        int k = kc >> 1, c0 = (kc & 1) * 32;
        const float* S = srcs[k];
        #pragma unroll
        for (int it = 0; it < 4; it++) {
            int idx = tid + it * 256;
            int r = idx >> 3, f4 = idx & 7;
            float4 v = *(const float4*)(S + (long long)(n0+r)*HH + c0 + f4*4);
            uint4 w = make_uint4(f2tf32(v.x), f2tf32(v.y), f2tf32(v.z), f2tf32(v.w));
            *(uint4*)&sm.ld.As[r][f4*4] = w;
        }
        #pragma unroll
        for (int it = 0; it < 2; it++) {       // W: 32 rows x 16 float4
            int idx = tid + it * 256;
            int j = idx >> 4, f4 = idx & 15;
            float4 v = *(const float4*)(WB + (long long)(k*65 + 1 + c0 + j)*O2 + f4*4);
            uint4 w = make_uint4(f2tf32(v.x), f2tf32(v.y), f2tf32(v.z), f2tf32(v.w));
            *(uint4*)&sm.ld.Ws[j][f4*4] = w;
        }
        __syncthreads();
        #pragma unroll
        for (int kk = 0; kk < 4; kk++) {
            uint32_t a[2][4], bfr[4][2];
            int ar = warpR * 32 + (lane >> 2);
            int ac = kk * 8 + (lane & 3);
            #pragma unroll
            for (int mm = 0; mm < 2; mm++) {
                a[mm][0] = sm.ld.As[ar + mm*16    ][ac];
                a[mm][1] = sm.ld.As[ar + mm*16 + 8][ac];
                a[mm][2] = sm.ld.As[ar + mm*16    ][ac + 4];
                a[mm][3] = sm.ld.As[ar + mm*16 + 8][ac + 4];
            }
            int bk = kk * 8 + (lane & 3);
            int bc = warpC * 32 + (lane >> 2);
            #pragma unroll
            for (int nn = 0; nn < 4; nn++) {
                bfr[nn][0] = sm.ld.Ws[bk    ][bc + nn*8];
                bfr[nn][1] = sm.ld.Ws[bk + 4][bc + nn*8];
            }
            #pragma unroll
            for (int mm = 0; mm < 2; mm++)
                #pragma unroll
                for (int nn = 0; nn < 4; nn++)
                    mma_tf32(acc[mm][nn], a[mm], bfr[nn]);
        }
        __syncthreads();
    }

    // GRU state into smem
    const float* b2B = g_b2 + b*O2;
    const float* deB = g_de + (long long)b*PS;
    const float* rgB = g_rg + (long long)b*PS;
    int r0l = warpR * 32 + (lane >> 2);
    int co = warpC * 32 + 2 * (lane & 3);
    #pragma unroll
    for (int mm = 0; mm < 2; mm++)
        #pragma unroll
        for (int nn = 0; nn < 4; nn++) {
            int o = co + nn*8;
            float bb0 = b2B[o], bb1 = b2B[o+1];
            #pragma unroll
            for (int half = 0; half < 2; half++) {
                int rl = r0l + mm*16 + half*8;
                int n = n0 + rl;
                float h0 = tanhf(acc[mm][nn][half*2+0] + bb0);
                float h1 = tanhf(acc[mm][nn][half*2+1] + bb1);
                float2 rr = *(const float2*)(rgB + (long long)n*HH + o);
                float2 dd = *(const float2*)(deB + (long long)n*HH + o);
                sm.st[rl][o]   = rr.x*dd.x + (1.f - rr.x)*h0;
                sm.st[rl][o+1] = rr.y*dd.y + (1.f - rr.y)*h1;
            }
        }
    __syncthreads();

    // final projection: out[bo][t][n] = state[n] . ow[t] + ob[t]
    int t = b % 12, bo = b / 12;
    if (tid < 128) {
        int nl = tid;
        float a = ob[t];
        #pragma unroll
        for (int h = 0; h < 64; h++) a = fmaf(sm.st[nl][h], ow[t*64+h], a);
        dout[(long long)bo*TT*NN + t*NN + n0 + nl] = a;
    }
}

// -------------------------------------------------------------------------
extern "C" void kernel_launch(void* const* d_in, const int* in_sizes, int n_in,
                              void* d_out, int out_size) {
    const float* hn  = (const float*)d_in[2];
    const float* ne1 = (const float*)d_in[3];
    const float* ne2 = (const float*)d_in[4];
    const float* E   = (const float*)d_in[5];
    const float* Wq  = (const float*)d_in[6];
    const float* bq  = (const float*)d_in[7];
    const float* Wk  = (const float*)d_in[8];
    const float* bk  = (const float*)d_in[9];
    const float* Wv  = (const float*)d_in[10];
    const float* bv  = (const float*)d_in[11];
    const float* taw = (const float*)d_in[12];
    const float* tab = (const float*)d_in[13];
    const float* gwp = (const float*)d_in[14];
    const float* gw  = (const float*)d_in[15];
    const float* gbp = (const float*)d_in[16];
    const float* gb  = (const float*)d_in[17];
    const float* uwp = (const float*)d_in[18];
    const float* uw  = (const float*)d_in[19];
    const float* ubp = (const float*)d_in[20];
    const float* ub  = (const float*)d_in[21];
    const float* ow  = (const float*)d_in[22];
    const float* ob  = (const float*)d_in[23];
    float* out = (float*)d_out;

    dim3 gprop(NN/128, BT);    // (4, 768)
    dim3 ggcn (NN/128, BT);

    k_adj<<<512, 512>>>(E);                                                    // 1
    k_attn_pre<<<BB, 64>>>(ne1, ne2, Wq, bq, Wk, bk, Wv, bv);                  // 2
    k_attn2<<<dim3(NN, BB), 128>>>(hn, Wq, Wk, Wv, taw, tab);                  // 3
    k_wgemm<<<dim3((3*65*O1)/64, BT/64), 256>>>(ne2, gwp, gw, 0);              // 4
    k_wgemm<<<dim3((3*65*O2)/64, BT/64), 256>>>(ne2, uwp, uw, 1);              // 5
    k_prop_mma<<<gprop, 256>>>(1);   // p1 = A @ de                  (profiled) 6
    k_prop_mma<<<gprop, 256>>>(2);   // p2 = 2*A@p1 - de                        7
    k_wgemm<<<dim3(O1/64, BT/64), 256>>>(ne2, gbp, gb, 2);                     // 8
    k_wgemm<<<dim3(O2/64, BT/64), 256>>>(ne2, ubp, ub, 3);                     // 9
    k_gcn1_mma<<<ggcn, 256>>>();     // -> y, rg                               10
    k_prop_mma<<<gprop, 256>>>(3);   // p1 = A @ y                             11
    k_prop_mma<<<gprop, 256>>>(4);   // p2 = 2*A@p1 - y                        12
    k_gcn2_mma<<<ggcn, 256>>>(ow, ob, out);                                    // 13
}

// round 7
// speedup vs baseline: 4.1774x; 1.2410x over previous
#include <cuda_runtime.h>
#include <cuda_fp16.h>
#include <cstdint>
#include <math.h>

#define BB 64
#define TT 12
#define BT 768          // BB*TT
#define NN 512
#define HH 64
#define TDD 32
#define O1 128
#define O2 64
#define PS (NN*HH)      // per-slice elements

// ---------------- scratch (device globals; no allocation) ----------------
__device__ __half g_Ah [NN*NN];               // adjacency, half
__device__ float  g_de [BT*NN*HH];            // de_input (f32, for GRU epilogues)
__device__ __half g_deh[BT*NN*HH];            // de_input, half (mma operand)
__device__ __half g_yh [BT*NN*HH];            // y = z*de, half
__device__ float  g_rg [BT*NN*HH];            // reset gate (f32)
__device__ __half g_p1h[BT*NN*HH];            // A @ x, half
__device__ __half g_p2h[BT*NN*HH];            // s2 = 2*A@(A@x) - x, half
__device__ __half g_W1h[BT*3*65*O1];          // per-(b,t) gcn1 weights, half
__device__ __half g_W2h[BT*3*65*O2];          // per-(b,t) gcn2 weights, half
__device__ float  g_b1[BT*O1];
__device__ float  g_b2[BT*O2];
__device__ float  g_spk[BB*64];               // per-b k bias part
__device__ float  g_spv[BB*64];               // per-b v bias part
__device__ float  g_sqq[BB*TT*64];            // per-(b,t) q bias part

// ---------------- mma/ldmatrix helpers (sm_80 PTX, ok on compute_103) -----
__device__ __forceinline__ uint32_t s2u(const void* p) {
    return (uint32_t)__cvta_generic_to_shared(p);
}
__device__ __forceinline__ void ldsm_x4(uint32_t* r, uint32_t a) {
    asm volatile("ldmatrix.sync.aligned.m8n8.x4.shared.b16 {%0,%1,%2,%3}, [%4];"
        : "=r"(r[0]), "=r"(r[1]), "=r"(r[2]), "=r"(r[3]) : "r"(a));
}
__device__ __forceinline__ void ldsm_x4_t(uint32_t* r, uint32_t a) {
    asm volatile("ldmatrix.sync.aligned.m8n8.x4.trans.shared.b16 {%0,%1,%2,%3}, [%4];"
        : "=r"(r[0]), "=r"(r[1]), "=r"(r[2]), "=r"(r[3]) : "r"(a));
}
__device__ __forceinline__ void mma_f16(float* c, const uint32_t* a, const uint32_t* b) {
    asm volatile(
        "mma.sync.aligned.m16n8k16.row.col.f32.f16.f16.f32 "
        "{%0,%1,%2,%3}, {%4,%5,%6,%7}, {%8,%9}, {%0,%1,%2,%3};"
        : "+f"(c[0]), "+f"(c[1]), "+f"(c[2]), "+f"(c[3])
        : "r"(a[0]), "r"(a[1]), "r"(a[2]), "r"(a[3]), "r"(b[0]), "r"(b[1]));
}

// ============ propagation: Y[p][n][c] = sum_m A[n][m] X[p][m][c]  (fp16) ===
// mode 1: deh->p1h  mode 2: p2h = 2*(A@p1h) - deh  mode 3: yh->p1h  mode 4: p2h = 2*(A@p1h) - yh
__global__ void __launch_bounds__(256) k_prop_mma(int mode) {
    const __half* X; __half* Y; const __half* X0 = g_deh;
    if (mode == 1)      { X = g_deh; Y = g_p1h; }
    else if (mode == 3) { X = g_yh;  Y = g_p1h; }
    else                { X = g_p1h; Y = g_p2h; X0 = (mode == 2) ? g_deh : g_yh; }
    const bool s2m = (mode == 2) || (mode == 4);

    __shared__ __align__(16) __half As[128][40];
    __shared__ __align__(16) __half Xs[32][72];

    int tid = threadIdx.x;
    int wid = tid >> 5, lane = tid & 31;
    int warpR = wid >> 1, warpC = wid & 1;
    int n0 = blockIdx.x * 128;
    const __half* Xp  = X  + (long long)blockIdx.y * PS;
    const __half* X0p = X0 + (long long)blockIdx.y * PS;
    __half*       Yp  = Y  + (long long)blockIdx.y * PS;

    float acc[2][4][4];
    #pragma unroll
    for (int mm=0;mm<2;mm++)
        #pragma unroll
        for (int nn=0;nn<4;nn++)
            #pragma unroll
            for (int q=0;q<4;q++) acc[mm][nn][q] = 0.f;

    int lrow = lane & 15, lcol = (lane >> 4) << 3;

    for (int kc = 0; kc < 16; kc++) {
        #pragma unroll
        for (int it = 0; it < 2; it++) {           // A: 128 rows x 4 uint4
            int idx = tid + it * 256;
            int r = idx >> 2, f = idx & 3;
            *(uint4*)&As[r][f*8] =
                *(const uint4*)(g_Ah + (long long)(n0+r)*NN + kc*32 + f*8);
        }
        {                                           // X: 32 rows x 8 uint4
            int k = tid >> 3, f = tid & 7;
            *(uint4*)&Xs[k][f*8] =
                *(const uint4*)(Xp + (long long)(kc*32 + k)*HH + f*8);
        }
        __syncthreads();

        #pragma unroll
        for (int k16 = 0; k16 < 2; k16++) {
            uint32_t a[2][4], bf[2][4];
            #pragma unroll
            for (int mm = 0; mm < 2; mm++)
                ldsm_x4(a[mm], s2u(&As[warpR*32 + mm*16 + lrow][k16*16 + lcol]));
            #pragma unroll
            for (int g = 0; g < 2; g++)
                ldsm_x4_t(bf[g], s2u(&Xs[k16*16 + lrow][warpC*32 + g*16 + lcol]));
            #pragma unroll
            for (int mm = 0; mm < 2; mm++)
                #pragma unroll
                for (int g = 0; g < 2; g++) {
                    mma_f16(acc[mm][g*2+0], a[mm], &bf[g][0]);
                    mma_f16(acc[mm][g*2+1], a[mm], &bf[g][2]);
                }
        }
        __syncthreads();
    }

    int r0 = n0 + warpR * 32 + (lane >> 2);
    int c0 = warpC * 32 + 2 * (lane & 3);
    #pragma unroll
    for (int mm = 0; mm < 2; mm++)
        #pragma unroll
        for (int nn = 0; nn < 4; nn++) {
            int r = r0 + mm*16, c = c0 + nn*8;
            float v00 = acc[mm][nn][0], v01 = acc[mm][nn][1];
            float v10 = acc[mm][nn][2], v11 = acc[mm][nn][3];
            if (s2m) {
                __half2 xa = *(const __half2*)(X0p + (long long)r*HH + c);
                __half2 xb = *(const __half2*)(X0p + (long long)(r+8)*HH + c);
                v00 = 2.f*v00 - __half2float(xa.x);
                v01 = 2.f*v01 - __half2float(xa.y);
                v10 = 2.f*v10 - __half2float(xb.x);
                v11 = 2.f*v11 - __half2float(xb.y);
            }
            *(__half2*)(Yp + (long long)r*HH + c)     = __floats2half2_rn(v00, v01);
            *(__half2*)(Yp + (long long)(r+8)*HH + c) = __floats2half2_rn(v10, v11);
        }
}

// ---------------- adjacency: A = softmax_row(relu(E E^T)) -> half ---------
__global__ void k_adj(const float* __restrict__ E) {
    int n = blockIdx.x;
    int m = threadIdx.x;               // 512 threads
    __shared__ float en[16];
    __shared__ float red[512];
    if (m < 16) en[m] = E[n*16 + m];
    __syncthreads();
    float s = 0.f;
    #pragma unroll
    for (int j = 0; j < 16; j++) s = fmaf(en[j], E[m*16 + j], s);
    s = fmaxf(s, 0.f);
    red[m] = s; __syncthreads();
    for (int off = 256; off > 0; off >>= 1) {
        if (m < off) red[m] = fmaxf(red[m], red[m+off]);
        __syncthreads();
    }
    float mx = red[0]; __syncthreads();
    float e = expf(s - mx);
    red[m] = e; __syncthreads();
    for (int off = 256; off > 0; off >>= 1) {
        if (m < off) red[m] += red[m+off];
        __syncthreads();
    }
    g_Ah[n*NN + m] = __float2half_rn(e / red[0]);
}

// ---------------- attention prelude: per-b / per-(b,t) bias parts --------
__global__ void k_attn_pre(const float* __restrict__ ne1, const float* __restrict__ ne2,
                           const float* __restrict__ Wq, const float* __restrict__ bq,
                           const float* __restrict__ Wk, const float* __restrict__ bk,
                           const float* __restrict__ Wv, const float* __restrict__ bv) {
    int b = blockIdx.x;
    int h = threadIdx.x;               // 64 threads
    __shared__ float sp[32], sq[TT*TDD];
    if (h < 32) sp[h] = ne1[b*TT*TDD + 11*TDD + h];
    for (int i = h; i < TT*TDD; i += 64) sq[i] = ne2[b*TT*TDD + i];
    __syncthreads();
    float ak = bk[h], av = bv[h];
    #pragma unroll
    for (int j = 0; j < 32; j++) {
        ak = fmaf(sp[j], Wk[j*64+h], ak);
        av = fmaf(sp[j], Wv[j*64+h], av);
    }
    g_spk[b*64+h] = ak;
    g_spv[b*64+h] = av;
    #pragma unroll
    for (int t = 0; t < TT; t++) {
        float a = bq[h];
        #pragma unroll
        for (int j = 0; j < 32; j++) a = fmaf(sq[t*32+j], Wq[j*64+h], a);
        g_sqq[(b*TT+t)*64+h] = a;
    }
}

// ---------------- temporal attention main -> de_input (f32 + half) -------
__global__ void k_attn2(const float* __restrict__ hn,
                        const float* __restrict__ Wq, const float* __restrict__ Wk,
                        const float* __restrict__ Wv,
                        const float* __restrict__ taw, const float* __restrict__ tab) {
    int n = blockIdx.x, b = blockIdx.y;
    int tid = threadIdx.x;             // 128
    __shared__ float xs[64], ks[64], vs[64], xq[64], t1[64], lg[96], vw[TT*64], sqs[TT*64];

    if (tid < 64) xs[tid] = hn[((long long)b*NN + n)*HH + tid];
    for (int i = tid; i < TT*64; i += 128) sqs[i] = g_sqq[b*TT*64 + i];
    __syncthreads();

    {
        int h = tid & 63;
        if (tid < 64) {
            float a = g_spk[b*64+h], a2 = 0.f;
            #pragma unroll
            for (int j = 0; j < 64; j++) {
                a  = fmaf(xs[j], Wk[(32+j)*64+h], a);
                a2 = fmaf(xs[j], Wq[(32+j)*64+h], a2);
            }
            ks[h] = fmaxf(a, 0.f);
            xq[h] = a2;
        } else {
            float a = g_spv[b*64+h], a2 = tab[h];
            #pragma unroll
            for (int j = 0; j < 64; j++) {
                a  = fmaf(xs[j], Wv[(32+j)*64+h], a);
                a2 = fmaf(xs[j], taw[j*64+h], a2);
            }
            vs[h] = fmaxf(a, 0.f);
            t1[h] = a2;
        }
    }
    __syncthreads();
    if (tid < 96) {
        int d = tid / 12, t = tid % 12;
        float a = 0.f;
        #pragma unroll
        for (int c = 0; c < 8; c++) {
            int h = d*8 + c;
            float q = fmaxf(xq[h] + sqs[t*64+h], 0.f);
            a = fmaf(q, ks[h], a);
        }
        lg[d*12+t] = a;
    }
    __syncthreads();
    if (tid < 8) {
        int d = tid;
        float mx = -1e30f;
        for (int t = 0; t < 12; t++) mx = fmaxf(mx, lg[d*12+t]);
        float s = 0.f;
        for (int t = 0; t < 12; t++) { float e = expf(lg[d*12+t]-mx); lg[d*12+t] = e; s += e; }
        float inv = 1.f/s;
        for (int t = 0; t < 12; t++) lg[d*12+t] *= inv;
    }
    __syncthreads();
    for (int idx = tid; idx < TT*64; idx += 128) {
        int t = idx >> 6, i = idx & 63;
        vw[idx] = lg[(i>>3)*12 + t] * vs[i];
    }
    __syncthreads();
    for (int idx = tid; idx < TT*64; idx += 128) {
        int t = idx >> 6, h = idx & 63;
        float a = t1[h];
        #pragma unroll
        for (int i = 0; i < 64; i++) a = fmaf(vw[t*64+i], taw[4096 + i*64 + h], a);
        long long o = ((long long)(b*12+t)*NN + n)*HH + h;
        g_de[o]  = a;
        g_deh[o] = __float2half_rn(a);
    }
}

// ---------------- per-(b,t) weights: temb@B + bias -> half W / f32 bias ---
__global__ void k_wgemm(const float* __restrict__ Am, const float* __restrict__ Bm,
                        const float* __restrict__ bias, int mode) {
    __half* Ch = nullptr; float* Cf = nullptr; int Nc;
    if (mode == 0)      { Ch = g_W1h; Nc = 3*65*O1; }
    else if (mode == 1) { Ch = g_W2h; Nc = 3*65*O2; }
    else if (mode == 2) { Cf = g_b1; Nc = O1; }
    else                { Cf = g_b2; Nc = O2; }

    __shared__ float At[32][65];
    __shared__ float Bt[32][64];
    int q0 = blockIdx.x * 64;
    int m0 = blockIdx.y * 64;
    int tid = threadIdx.x;
    int tx = tid & 15, ty = tid >> 4;
    #pragma unroll
    for (int p=0;p<8;p++) {
        int idx = tid + p*256;
        int d = idx & 31, m = idx >> 5;
        At[d][m] = Am[(m0+m)*32 + d];
    }
    #pragma unroll
    for (int p=0;p<8;p++) {
        int idx = tid + p*256;
        int q = idx & 63, d = idx >> 6;
        Bt[d][q] = Bm[(long long)d*Nc + q0 + q];
    }
    __syncthreads();
    float acc[4][4] = {};
    #pragma unroll
    for (int d=0; d<32; d++) {
        float a[4];
        #pragma unroll
        for (int i=0;i<4;i++) a[i] = At[d][ty*4+i];
        float4 b4 = *(const float4*)&Bt[d][tx*4];
        float bv[4] = {b4.x,b4.y,b4.z,b4.w};
        #pragma unroll
        for (int i=0;i<4;i++)
            #pragma unroll
            for (int j=0;j<4;j++) acc[i][j] = fmaf(a[i], bv[j], acc[i][j]);
    }
    float4 bb = *(const float4*)&bias[q0 + tx*4];
    float bs[4] = {bb.x,bb.y,bb.z,bb.w};
    #pragma unroll
    for (int i=0;i<4;i++) {
        float v0 = acc[i][0]+bs[0], v1 = acc[i][1]+bs[1];
        float v2 = acc[i][2]+bs[2], v3 = acc[i][3]+bs[3];
        long long off = (long long)(m0+ty*4+i)*Nc + q0 + tx*4;
        if (Ch) {
            __half2 h0 = __floats2half2_rn(v0, v1);
            __half2 h1 = __floats2half2_rn(v2, v3);
            *(__half2*)(Ch + off)     = h0;
            *(__half2*)(Ch + off + 2) = h1;
        } else {
            *(float4*)(Cf + off) = make_float4(v0, v1, v2, v3);
        }
    }
}

// ======== gcn1 (fp16 mma): zr = sigmoid(xg@W1+b1) -> yh = z*de, rg ========
// CTA 128 nodes x 128 outs, K=192 in 6 chunks of 32. warp tile 32x64.
__global__ void __launch_bounds__(256) k_gcn1_mma() {
    __shared__ __align__(16) __half As[128][40];
    __shared__ __align__(16) __half Ws[32][136];
    int tid = threadIdx.x;
    int wid = tid >> 5, lane = tid & 31;
    int warpR = wid >> 1, warpC = wid & 1;
    int n0 = blockIdx.x * 128;
    int b  = blockIdx.y;
    const __half* srcs[3] = { g_deh + (long long)b*PS, g_p1h + (long long)b*PS, g_p2h + (long long)b*PS };
    const __half* WB = g_W1h + (long long)b*3*65*O1;

    float acc[2][8][4];
    #pragma unroll
    for (int mm=0;mm<2;mm++)
        #pragma unroll
        for (int nn=0;nn<8;nn++)
            #pragma unroll
            for (int q=0;q<4;q++) acc[mm][nn][q] = 0.f;

    int lrow = lane & 15, lcol = (lane >> 4) << 3;

    for (int kc = 0; kc < 6; kc++) {
        int k = kc >> 1, c0 = (kc & 1) * 32;
        const __half* S = srcs[k];
        #pragma unroll
        for (int it = 0; it < 2; it++) {       // A: 128 rows x 4 uint4
            int idx = tid + it * 256;
            int r = idx >> 2, f = idx & 3;
            *(uint4*)&As[r][f*8] = *(const uint4*)(S + (long long)(n0+r)*HH + c0 + f*8);
        }
        #pragma unroll
        for (int it = 0; it < 2; it++) {       // W: 32 rows x 16 uint4
            int idx = tid + it * 256;
            int j = idx >> 4, f = idx & 15;
            *(uint4*)&Ws[j][f*8] = *(const uint4*)(WB + (long long)(k*65 + 1 + c0 + j)*O1 + f*8);
        }
        __syncthreads();
        #pragma unroll
        for (int k16 = 0; k16 < 2; k16++) {
            uint32_t a[2][4];
            #pragma unroll
            for (int mm = 0; mm < 2; mm++)
                ldsm_x4(a[mm], s2u(&As[warpR*32 + mm*16 + lrow][k16*16 + lcol]));
            #pragma unroll
            for (int g = 0; g < 4; g++) {
                uint32_t bf[4];
                ldsm_x4_t(bf, s2u(&Ws[k16*16 + lrow][warpC*64 + g*16 + lcol]));
                #pragma unroll
                for (int mm = 0; mm < 2; mm++) {
                    mma_f16(acc[mm][g*2+0], a[mm], &bf[0]);
                    mma_f16(acc[mm][g*2+1], a[mm], &bf[2]);
                }
            }
        }
        __syncthreads();
    }

    const float* b1B = g_b1 + b*O1;
    const float* deB = g_de + (long long)b*PS;
    __half* yB = g_yh + (long long)b*PS;
    float* rgB = g_rg + (long long)b*PS;
    int r0 = n0 + warpR * 32 + (lane >> 2);
    int co = warpC * 64 + 2 * (lane & 3);
    #pragma unroll
    for (int mm = 0; mm < 2; mm++)
        #pragma unroll
        for (int nn = 0; nn < 8; nn++) {
            int o = co + nn*8;
            float bb0 = b1B[o], bb1 = b1B[o+1];
            #pragma unroll
            for (int half_ = 0; half_ < 2; half_++) {
                int r = r0 + mm*16 + half_*8;
                float s0 = 1.f/(1.f + expf(-(acc[mm][nn][half_*2+0] + bb0)));
                float s1 = 1.f/(1.f + expf(-(acc[mm][nn][half_*2+1] + bb1)));
                if (warpC == 0) {      // o in [0,64): z -> y = z*de (half)
                    float2 d = *(const float2*)(deB + (long long)r*HH + o);
                    *(__half2*)(yB + (long long)r*HH + o) = __floats2half2_rn(s0*d.x, s1*d.y);
                } else {               // o in [64,128): rg (f32)
                    *(float2*)(rgB + (long long)r*HH + (o-64)) = make_float2(s0, s1);
                }
            }
        }
}

// ======== gcn2 (fp16 mma): hc = tanh(.), GRU state, time projection =======
__global__ void __launch_bounds__(256) k_gcn2_mma(const float* __restrict__ ow,
                                                  const float* __restrict__ ob,
                                                  float* __restrict__ dout) {
    __shared__ __align__(16) union {
        struct { __half As[128][40]; __half Ws[32][72]; } ld;
        float st[128][65];
    } sm;
    int tid = threadIdx.x;
    int wid = tid >> 5, lane = tid & 31;
    int warpR = wid >> 1, warpC = wid & 1;
    int n0 = blockIdx.x * 128;
    int b  = blockIdx.y;
    const __half* srcs[3] = { g_yh + (long long)b*PS, g_p1h + (long long)b*PS, g_p2h + (long long)b*PS };
    const __half* WB = g_W2h + (long long)b*3*65*O2;

    float acc[2][4][4];
    #pragma unroll
    for (int mm=0;mm<2;mm++)
        #pragma unroll
        for (int nn=0;nn<4;nn++)
            #pragma unroll
            for (int q=0;q<4;q++) acc[mm][nn][q] = 0.f;

    int lrow = lane & 15, lcol = (lane >> 4) << 3;

    for (int kc = 0; kc < 6; kc++) {
        int k = kc >> 1, c0 = (kc & 1) * 32;
        const __half* S = srcs[k];
        #pragma unroll
        for (int it = 0; it < 2; it++) {
            int idx = tid + it * 256;
            int r = idx >> 2, f = idx & 3;
            *(uint4*)&sm.ld.As[r][f*8] = *(const uint4*)(S + (long long)(n0+r)*HH + c0 + f*8);
        }
        {                                       // W: 32 rows x 8 uint4
            int j = tid >> 3, f = tid & 7;
            *(uint4*)&sm.ld.Ws[j][f*8] = *(const uint4*)(WB + (long long)(k*65 + 1 + c0 + j)*O2 + f*8);
        }
        __syncthreads();
        #pragma unroll
        for (int k16 = 0; k16 < 2; k16++) {
            uint32_t a[2][4], bf[2][4];
            #pragma unroll
            for (int mm = 0; mm < 2; mm++)
                ldsm_x4(a[mm], s2u(&sm.ld.As[warpR*32 + mm*16 + lrow][k16*16 + lcol]));
            #pragma unroll
            for (int g = 0; g < 2; g++)
                ldsm_x4_t(bf[g], s2u(&sm.ld.Ws[k16*16 + lrow][warpC*32 + g*16 + lcol]));
            #pragma unroll
            for (int mm = 0; mm < 2; mm++)
                #pragma unroll
                for (int g = 0; g < 2; g++) {
                    mma_f16(acc[mm][g*2+0], a[mm], &bf[g][0]);
                    mma_f16(acc[mm][g*2+1], a[mm], &bf[g][2]);
                }
        }
        __syncthreads();
    }

    const float* b2B = g_b2 + b*O2;
    const float* deB = g_de + (long long)b*PS;
    const float* rgB = g_rg + (long long)b*PS;
    int r0l = warpR * 32 + (lane >> 2);
    int co = warpC * 32 + 2 * (lane & 3);
    #pragma unroll
    for (int mm = 0; mm < 2; mm++)
        #pragma unroll
        for (int nn = 0; nn < 4; nn++) {
            int o = co + nn*8;
            float bb0 = b2B[o], bb1 = b2B[o+1];
            #pragma unroll
            for (int half_ = 0; half_ < 2; half_++) {
                int rl = r0l + mm*16 + half_*8;
                int n = n0 + rl;
                float h0 = tanhf(acc[mm][nn][half_*2+0] + bb0);
                float h1 = tanhf(acc[mm][nn][half_*2+1] + bb1);
                float2 rr = *(const float2*)(rgB + (long long)n*HH + o);
                float2 dd = *(const float2*)(deB + (long long)n*HH + o);
                sm.st[rl][o]   = rr.x*dd.x + (1.f - rr.x)*h0;
                sm.st[rl][o+1] = rr.y*dd.y + (1.f - rr.y)*h1;
            }
        }
    __syncthreads();

    int t = b % 12, bo = b / 12;
    if (tid < 128) {
        int nl = tid;
        float a = ob[t];
        #pragma unroll
        for (int h = 0; h < 64; h++) a = fmaf(sm.st[nl][h], ow[t*64+h], a);
        dout[(long long)bo*TT*NN + t*NN + n0 + nl] = a;
    }
}

// -------------------------------------------------------------------------
extern "C" void kernel_launch(void* const* d_in, const int* in_sizes, int n_in,
                              void* d_out, int out_size) {
    const float* hn  = (const float*)d_in[2];
    const float* ne1 = (const float*)d_in[3];
    const float* ne2 = (const float*)d_in[4];
    const float* E   = (const float*)d_in[5];
    const float* Wq  = (const float*)d_in[6];
    const float* bq  = (const float*)d_in[7];
    const float* Wk  = (const float*)d_in[8];
    const float* bk  = (const float*)d_in[9];
    const float* Wv  = (const float*)d_in[10];
    const float* bv  = (const float*)d_in[11];
    const float* taw = (const float*)d_in[12];
    const float* tab = (const float*)d_in[13];
    const float* gwp = (const float*)d_in[14];
    const float* gw  = (const float*)d_in[15];
    const float* gbp = (const float*)d_in[16];
    const float* gb  = (const float*)d_in[17];
    const float* uwp = (const float*)d_in[18];
    const float* uw  = (const float*)d_in[19];
    const float* ubp = (const float*)d_in[20];
    const float* ub  = (const float*)d_in[21];
    const float* ow  = (const float*)d_in[22];
    const float* ob  = (const float*)d_in[23];
    float* out = (float*)d_out;

    dim3 gprop(NN/128, BT);    // (4, 768)
    dim3 ggcn (NN/128, BT);

    k_adj<<<512, 512>>>(E);
    k_attn_pre<<<BB, 64>>>(ne1, ne2, Wq, bq, Wk, bk, Wv, bv);
    k_attn2<<<dim3(NN, BB), 128>>>(hn, Wq, Wk, Wv, taw, tab);
    k_wgemm<<<dim3((3*65*O1)/64, BT/64), 256>>>(ne2, gwp, gw, 0);
    k_wgemm<<<dim3((3*65*O2)/64, BT/64), 256>>>(ne2, uwp, uw, 1);
    k_prop_mma<<<gprop, 256>>>(1);   // p1h = A @ deh
    k_prop_mma<<<gprop, 256>>>(2);   // p2h = 2*A@p1h - deh
    k_wgemm<<<dim3(O1/64, BT/64), 256>>>(ne2, gbp, gb, 2);
    k_wgemm<<<dim3(O2/64, BT/64), 256>>>(ne2, ubp, ub, 3);
    k_gcn1_mma<<<ggcn, 256>>>();     // -> yh, rg
    k_prop_mma<<<gprop, 256>>>(3);   // p1h = A @ yh
    k_prop_mma<<<gprop, 256>>>(4);   // p2h = 2*A@p1h - yh
    k_gcn2_mma<<<ggcn, 256>>>(ow, ob, out);
}

// round 8
// speedup vs baseline: 5.0359x; 1.2055x over previous
#include <cuda_runtime.h>
#include <cuda_fp16.h>
#include <cstdint>
#include <math.h>

#define BB 64
#define TT 12
#define BT 768          // BB*TT
#define NN 512
#define HH 64
#define TDD 32
#define O1 128
#define O2 64
#define PS (NN*HH)      // per-slice elements

// ---------------- scratch (device globals; no allocation) ----------------
__device__ __half g_Acat[2*NN*NN];            // rows 0..511: A, rows 512..1023: 2A^2-I
__device__ float  g_de [BT*NN*HH];            // de_input (f32, for GRU epilogues)
__device__ __half g_deh[BT*NN*HH];            // de_input, half (mma operand)
__device__ __half g_yh [BT*NN*HH];            // y = z*de, half
__device__ float  g_rg [BT*NN*HH];            // reset gate (f32)
__device__ __half g_p1h[BT*NN*HH];            // A @ x, half
__device__ __half g_p2h[BT*NN*HH];            // (2A^2-I) @ x, half
__device__ __half g_W1h[BT*3*65*O1];          // per-(b,t) gcn1 weights, half
__device__ __half g_W2h[BT*3*65*O2];          // per-(b,t) gcn2 weights, half
__device__ float  g_b1[BT*O1];
__device__ float  g_b2[BT*O2];
__device__ float  g_spk[BB*64];               // per-b k bias part
__device__ float  g_spv[BB*64];               // per-b v bias part
__device__ float  g_sqq[BB*TT*64];            // per-(b,t) q bias part

// ---------------- mma/ldmatrix/cp.async helpers (sm_80 PTX) ---------------
__device__ __forceinline__ uint32_t s2u(const void* p) {
    return (uint32_t)__cvta_generic_to_shared(p);
}
__device__ __forceinline__ void ldsm_x4(uint32_t* r, uint32_t a) {
    asm volatile("ldmatrix.sync.aligned.m8n8.x4.shared.b16 {%0,%1,%2,%3}, [%4];"
        : "=r"(r[0]), "=r"(r[1]), "=r"(r[2]), "=r"(r[3]) : "r"(a));
}
__device__ __forceinline__ void ldsm_x4_t(uint32_t* r, uint32_t a) {
    asm volatile("ldmatrix.sync.aligned.m8n8.x4.trans.shared.b16 {%0,%1,%2,%3}, [%4];"
        : "=r"(r[0]), "=r"(r[1]), "=r"(r[2]), "=r"(r[3]) : "r"(a));
}
__device__ __forceinline__ void mma_f16(float* c, const uint32_t* a, const uint32_t* b) {
    asm volatile(
        "mma.sync.aligned.m16n8k16.row.col.f32.f16.f16.f32 "
        "{%0,%1,%2,%3}, {%4,%5,%6,%7}, {%8,%9}, {%0,%1,%2,%3};"
        : "+f"(c[0]), "+f"(c[1]), "+f"(c[2]), "+f"(c[3])
        : "r"(a[0]), "r"(a[1]), "r"(a[2]), "r"(a[3]), "r"(b[0]), "r"(b[1]));
}
__device__ __forceinline__ void cp16(void* s, const void* g) {
    asm volatile("cp.async.ca.shared.global [%0], [%1], 16;" :: "r"(s2u(s)), "l"(g));
}
__device__ __forceinline__ void cp_commit() { asm volatile("cp.async.commit_group;"); }
__device__ __forceinline__ void cp_wait1()  { asm volatile("cp.async.wait_group 1;"); }
__device__ __forceinline__ void cp_wait0()  { asm volatile("cp.async.wait_group 0;"); }

// ---------------- adjacency: A = softmax_row(relu(E E^T)) -> half ---------
__global__ void k_adj(const float* __restrict__ E) {
    int n = blockIdx.x;
    int m = threadIdx.x;               // 512 threads
    __shared__ float en[16];
    __shared__ float red[512];
    if (m < 16) en[m] = E[n*16 + m];
    __syncthreads();
    float s = 0.f;
    #pragma unroll
    for (int j = 0; j < 16; j++) s = fmaf(en[j], E[m*16 + j], s);
    s = fmaxf(s, 0.f);
    red[m] = s; __syncthreads();
    for (int off = 256; off > 0; off >>= 1) {
        if (m < off) red[m] = fmaxf(red[m], red[m+off]);
        __syncthreads();
    }
    float mx = red[0]; __syncthreads();
    float e = expf(s - mx);
    red[m] = e; __syncthreads();
    for (int off = 256; off > 0; off >>= 1) {
        if (m < off) red[m] += red[m+off];
        __syncthreads();
    }
    g_Acat[n*NN + m] = __float2half_rn(e / red[0]);
}

// ---------------- A2' = 2*A@A - I  (fp16 mma, rows 512..1023 of Acat) -----
__global__ void __launch_bounds__(256) k_a2() {
    __shared__ __align__(16) __half As[128][40];
    __shared__ __align__(16) __half Bs[32][136];
    int tid = threadIdx.x;
    int wid = tid >> 5, lane = tid & 31;
    int warpR = wid >> 1, warpC = wid & 1;
    int n0 = blockIdx.x * 128;         // col tile
    int m0 = blockIdx.y * 128;         // row tile

    float acc[2][8][4];
    #pragma unroll
    for (int mm=0;mm<2;mm++)
        #pragma unroll
        for (int nn=0;nn<8;nn++)
            #pragma unroll
            for (int q=0;q<4;q++) acc[mm][nn][q] = 0.f;

    int lrow = lane & 15, lcol = (lane >> 4) << 3;

    for (int kc = 0; kc < 16; kc++) {
        #pragma unroll
        for (int it = 0; it < 2; it++) {       // A rows m-tile, k-chunk
            int idx = tid + it * 256;
            int r = idx >> 2, f = idx & 3;
            *(uint4*)&As[r][f*8] = *(const uint4*)(g_Acat + (long long)(m0+r)*NN + kc*32 + f*8);
        }
        #pragma unroll
        for (int it = 0; it < 2; it++) {       // A rows k, cols n-tile
            int idx = tid + it * 256;
            int j = idx >> 4, f = idx & 15;
            *(uint4*)&Bs[j][f*8] = *(const uint4*)(g_Acat + (long long)(kc*32+j)*NN + n0 + f*8);
        }
        __syncthreads();
        #pragma unroll
        for (int k16 = 0; k16 < 2; k16++) {
            uint32_t a[2][4];
            #pragma unroll
            for (int mm = 0; mm < 2; mm++)
                ldsm_x4(a[mm], s2u(&As[warpR*32 + mm*16 + lrow][k16*16 + lcol]));
            #pragma unroll
            for (int g = 0; g < 4; g++) {
                uint32_t bf[4];
                ldsm_x4_t(bf, s2u(&Bs[k16*16 + lrow][warpC*64 + g*16 + lcol]));
                #pragma unroll
                for (int mm = 0; mm < 2; mm++) {
                    mma_f16(acc[mm][g*2+0], a[mm], &bf[0]);
                    mma_f16(acc[mm][g*2+1], a[mm], &bf[2]);
                }
            }
        }
        __syncthreads();
    }

    int r0 = m0 + warpR * 32 + (lane >> 2);
    int co = n0 + warpC * 64 + 2 * (lane & 3);
    #pragma unroll
    for (int mm = 0; mm < 2; mm++)
        #pragma unroll
        for (int nn = 0; nn < 8; nn++) {
            int c = co + nn*8;
            #pragma unroll
            for (int half_ = 0; half_ < 2; half_++) {
                int r = r0 + mm*16 + half_*8;
                float v0 = 2.f*acc[mm][nn][half_*2+0] - (r == c   ? 1.f : 0.f);
                float v1 = 2.f*acc[mm][nn][half_*2+1] - (r == c+1 ? 1.f : 0.f);
                *(__half2*)(g_Acat + (long long)(NN + r)*NN + c) = __floats2half2_rn(v0, v1);
            }
        }
}

// ======= merged propagation: [p1; p2] = [A; 2A^2-I] @ X, double-buffered ===
// grid (8, 768): bx<4 -> p1 rows bx*128, bx>=4 -> p2 rows (bx-4)*128.
// mode 1: X = deh   mode 2: X = yh
__global__ void __launch_bounds__(256) k_prop2(int mode) {
    const __half* X = (mode == 1) ? g_deh : g_yh;
    __half* Y = (blockIdx.x < 4) ? g_p1h : g_p2h;
    int arow0 = blockIdx.x * 128;              // row into Acat (0..1023)
    int n0 = (blockIdx.x & 3) * 128;           // output row base

    __shared__ __align__(16) __half As[2][128][40];
    __shared__ __align__(16) __half Xs[2][32][72];

    int tid = threadIdx.x;
    int wid = tid >> 5, lane = tid & 31;
    int warpR = wid >> 1, warpC = wid & 1;
    const __half* Xp = X + (long long)blockIdx.y * PS;
    __half*       Yp = Y + (long long)blockIdx.y * PS;

    float acc[2][4][4];
    #pragma unroll
    for (int mm=0;mm<2;mm++)
        #pragma unroll
        for (int nn=0;nn<4;nn++)
            #pragma unroll
            for (int q=0;q<4;q++) acc[mm][nn][q] = 0.f;

    int lrow = lane & 15, lcol = (lane >> 4) << 3;

    // async stage of one chunk into buffer buf
    auto stage = [&](int kc, int buf) {
        #pragma unroll
        for (int it = 0; it < 2; it++) {       // A: 128 rows x 4 x 16B
            int idx = tid + it * 256;
            int r = idx >> 2, f = idx & 3;
            cp16(&As[buf][r][f*8], g_Acat + (long long)(arow0+r)*NN + kc*32 + f*8);
        }
        {                                       // X: 32 rows x 8 x 16B
            int k = tid >> 3, f = tid & 7;
            cp16(&Xs[buf][k][f*8], Xp + (long long)(kc*32 + k)*HH + f*8);
        }
        cp_commit();
    };

    stage(0, 0);
    for (int kc = 0; kc < 16; kc++) {
        int buf = kc & 1;
        if (kc < 15) stage(kc+1, buf ^ 1);
        if (kc < 15) cp_wait1(); else cp_wait0();
        __syncthreads();

        #pragma unroll
        for (int k16 = 0; k16 < 2; k16++) {
            uint32_t a[2][4], bf[2][4];
            #pragma unroll
            for (int mm = 0; mm < 2; mm++)
                ldsm_x4(a[mm], s2u(&As[buf][warpR*32 + mm*16 + lrow][k16*16 + lcol]));
            #pragma unroll
            for (int g = 0; g < 2; g++)
                ldsm_x4_t(bf[g], s2u(&Xs[buf][k16*16 + lrow][warpC*32 + g*16 + lcol]));
            #pragma unroll
            for (int mm = 0; mm < 2; mm++)
                #pragma unroll
                for (int g = 0; g < 2; g++) {
                    mma_f16(acc[mm][g*2+0], a[mm], &bf[g][0]);
                    mma_f16(acc[mm][g*2+1], a[mm], &bf[g][2]);
                }
        }
        __syncthreads();
    }

    int r0 = n0 + warpR * 32 + (lane >> 2);
    int c0 = warpC * 32 + 2 * (lane & 3);
    #pragma unroll
    for (int mm = 0; mm < 2; mm++)
        #pragma unroll
        for (int nn = 0; nn < 4; nn++) {
            int r = r0 + mm*16, c = c0 + nn*8;
            *(__half2*)(Yp + (long long)r*HH + c) =
                __floats2half2_rn(acc[mm][nn][0], acc[mm][nn][1]);
            *(__half2*)(Yp + (long long)(r+8)*HH + c) =
                __floats2half2_rn(acc[mm][nn][2], acc[mm][nn][3]);
        }
}

// ---------------- attention prelude: per-b / per-(b,t) bias parts --------
__global__ void k_attn_pre(const float* __restrict__ ne1, const float* __restrict__ ne2,
                           const float* __restrict__ Wq, const float* __restrict__ bq,
                           const float* __restrict__ Wk, const float* __restrict__ bk,
                           const float* __restrict__ Wv, const float* __restrict__ bv) {
    int b = blockIdx.x;
    int h = threadIdx.x;               // 64 threads
    __shared__ float sp[32], sq[TT*TDD];
    if (h < 32) sp[h] = ne1[b*TT*TDD + 11*TDD + h];
    for (int i = h; i < TT*TDD; i += 64) sq[i] = ne2[b*TT*TDD + i];
    __syncthreads();
    float ak = bk[h], av = bv[h];
    #pragma unroll
    for (int j = 0; j < 32; j++) {
        ak = fmaf(sp[j], Wk[j*64+h], ak);
        av = fmaf(sp[j], Wv[j*64+h], av);
    }
    g_spk[b*64+h] = ak;
    g_spv[b*64+h] = av;
    #pragma unroll
    for (int t = 0; t < TT; t++) {
        float a = bq[h];
        #pragma unroll
        for (int j = 0; j < 32; j++) a = fmaf(sq[t*32+j], Wq[j*64+h], a);
        g_sqq[(b*TT+t)*64+h] = a;
    }
}

// ------- temporal attention main (rank-8 factorized) -> de_input ---------
__global__ void k_attn2(const float* __restrict__ hn,
                        const float* __restrict__ Wq, const float* __restrict__ Wk,
                        const float* __restrict__ Wv,
                        const float* __restrict__ taw, const float* __restrict__ tab) {
    int n = blockIdx.x, b = blockIdx.y;
    int tid = threadIdx.x;             // 128
    __shared__ float xs[64], ks[64], vs[64], xq[64], t1[64], lg[96], us[8][64], sqs[TT*64];

    if (tid < 64) xs[tid] = hn[((long long)b*NN + n)*HH + tid];
    for (int i = tid; i < TT*64; i += 128) sqs[i] = g_sqq[b*TT*64 + i];
    __syncthreads();

    {
        int h = tid & 63;
        if (tid < 64) {
            float a = g_spk[b*64+h], a2 = 0.f;
            #pragma unroll
            for (int j = 0; j < 64; j++) {
                a  = fmaf(xs[j], Wk[(32+j)*64+h], a);
                a2 = fmaf(xs[j], Wq[(32+j)*64+h], a2);
            }
            ks[h] = fmaxf(a, 0.f);
            xq[h] = a2;
        } else {
            float a = g_spv[b*64+h], a2 = tab[h];
            #pragma unroll
            for (int j = 0; j < 64; j++) {
                a  = fmaf(xs[j], Wv[(32+j)*64+h], a);
                a2 = fmaf(xs[j], taw[j*64+h], a2);
            }
            vs[h] = fmaxf(a, 0.f);
            t1[h] = a2;
        }
    }
    __syncthreads();
    if (tid < 96) {                    // logits per (head d, time t)
        int d = tid / 12, t = tid % 12;
        float a = 0.f;
        #pragma unroll
        for (int c = 0; c < 8; c++) {
            int h = d*8 + c;
            float q = fmaxf(xq[h] + sqs[t*64+h], 0.f);
            a = fmaf(q, ks[h], a);
        }
        lg[d*12+t] = a;
    }
    __syncthreads();
    if (tid < 8) {                     // softmax over t
        int d = tid;
        float mx = -1e30f;
        for (int t = 0; t < 12; t++) mx = fmaxf(mx, lg[d*12+t]);
        float s = 0.f;
        for (int t = 0; t < 12; t++) { float e = expf(lg[d*12+t]-mx); lg[d*12+t] = e; s += e; }
        float inv = 1.f/s;
        for (int t = 0; t < 12; t++) lg[d*12+t] *= inv;
    }
    __syncthreads();
    // u[d][h] = sum_{i in head d} vs[i] * taw2[i][h]   (rank-8 factor)
    for (int idx = tid; idx < 512; idx += 128) {
        int d = idx >> 6, h = idx & 63;
        float a = 0.f;
        #pragma unroll
        for (int c = 0; c < 8; c++) {
            int i = d*8 + c;
            a = fmaf(vs[i], taw[4096 + i*64 + h], a);
        }
        us[d][h] = a;
    }
    __syncthreads();
    for (int idx = tid; idx < TT*64; idx += 128) {
        int t = idx >> 6, h = idx & 63;
        float a = t1[h];
        #pragma unroll
        for (int d = 0; d < 8; d++) a = fmaf(lg[d*12+t], us[d][h], a);
        long long o = ((long long)(b*12+t)*NN + n)*HH + h;
        g_de[o]  = a;
        g_deh[o] = __float2half_rn(a);
    }
}

// ---------------- per-(b,t) weights: temb@B + bias -> half W / f32 bias ---
__global__ void k_wgemm(const float* __restrict__ Am, const float* __restrict__ Bm,
                        const float* __restrict__ bias, int mode) {
    __half* Ch = nullptr; float* Cf = nullptr; int Nc;
    if (mode == 0)      { Ch = g_W1h; Nc = 3*65*O1; }
    else if (mode == 1) { Ch = g_W2h; Nc = 3*65*O2; }
    else if (mode == 2) { Cf = g_b1; Nc = O1; }
    else                { Cf = g_b2; Nc = O2; }

    __shared__ float At[32][65];
    __shared__ float Bt[32][64];
    int q0 = blockIdx.x * 64;
    int m0 = blockIdx.y * 64;
    int tid = threadIdx.x;
    int tx = tid & 15, ty = tid >> 4;
    #pragma unroll
    for (int p=0;p<8;p++) {
        int idx = tid + p*256;
        int d = idx & 31, m = idx >> 5;
        At[d][m] = Am[(m0+m)*32 + d];
    }
    #pragma unroll
    for (int p=0;p<8;p++) {
        int idx = tid + p*256;
        int q = idx & 63, d = idx >> 6;
        Bt[d][q] = Bm[(long long)d*Nc + q0 + q];
    }
    __syncthreads();
    float acc[4][4] = {};
    #pragma unroll
    for (int d=0; d<32; d++) {
        float a[4];
        #pragma unroll
        for (int i=0;i<4;i++) a[i] = At[d][ty*4+i];
        float4 b4 = *(const float4*)&Bt[d][tx*4];
        float bv[4] = {b4.x,b4.y,b4.z,b4.w};
        #pragma unroll
        for (int i=0;i<4;i++)
            #pragma unroll
            for (int j=0;j<4;j++) acc[i][j] = fmaf(a[i], bv[j], acc[i][j]);
    }
    float4 bb = *(const float4*)&bias[q0 + tx*4];
    float bs[4] = {bb.x,bb.y,bb.z,bb.w};
    #pragma unroll
    for (int i=0;i<4;i++) {
        float v0 = acc[i][0]+bs[0], v1 = acc[i][1]+bs[1];
        float v2 = acc[i][2]+bs[2], v3 = acc[i][3]+bs[3];
        long long off = (long long)(m0+ty*4+i)*Nc + q0 + tx*4;
        if (Ch) {
            *(__half2*)(Ch + off)     = __floats2half2_rn(v0, v1);
            *(__half2*)(Ch + off + 2) = __floats2half2_rn(v2, v3);
        } else {
            *(float4*)(Cf + off) = make_float4(v0, v1, v2, v3);
        }
    }
}

// ======== gcn1 (fp16 mma): zr = sigmoid(xg@W1+b1) -> yh = z*de, rg ========
__global__ void __launch_bounds__(256) k_gcn1_mma() {
    __shared__ __align__(16) __half As[128][40];
    __shared__ __align__(16) __half Ws[32][136];
    int tid = threadIdx.x;
    int wid = tid >> 5, lane = tid & 31;
    int warpR = wid >> 1, warpC = wid & 1;
    int n0 = blockIdx.x * 128;
    int b  = blockIdx.y;
    const __half* srcs[3] = { g_deh + (long long)b*PS, g_p1h + (long long)b*PS, g_p2h + (long long)b*PS };
    const __half* WB = g_W1h + (long long)b*3*65*O1;

    float acc[2][8][4];
    #pragma unroll
    for (int mm=0;mm<2;mm++)
        #pragma unroll
        for (int nn=0;nn<8;nn++)
            #pragma unroll
            for (int q=0;q<4;q++) acc[mm][nn][q] = 0.f;

    int lrow = lane & 15, lcol = (lane >> 4) << 3;

    for (int kc = 0; kc < 6; kc++) {
        int k = kc >> 1, c0 = (kc & 1) * 32;
        const __half* S = srcs[k];
        #pragma unroll
        for (int it = 0; it < 2; it++) {
            int idx = tid + it * 256;
            int r = idx >> 2, f = idx & 3;
            *(uint4*)&As[r][f*8] = *(const uint4*)(S + (long long)(n0+r)*HH + c0 + f*8);
        }
        #pragma unroll
        for (int it = 0; it < 2; it++) {
            int idx = tid + it * 256;
            int j = idx >> 4, f = idx & 15;
            *(uint4*)&Ws[j][f*8] = *(const uint4*)(WB + (long long)(k*65 + 1 + c0 + j)*O1 + f*8);
        }
        __syncthreads();
        #pragma unroll
        for (int k16 = 0; k16 < 2; k16++) {
            uint32_t a[2][4];
            #pragma unroll
            for (int mm = 0; mm < 2; mm++)
                ldsm_x4(a[mm], s2u(&As[warpR*32 + mm*16 + lrow][k16*16 + lcol]));
            #pragma unroll
            for (int g = 0; g < 4; g++) {
                uint32_t bf[4];
                ldsm_x4_t(bf, s2u(&Ws[k16*16 + lrow][warpC*64 + g*16 + lcol]));
                #pragma unroll
                for (int mm = 0; mm < 2; mm++) {
                    mma_f16(acc[mm][g*2+0], a[mm], &bf[0]);
                    mma_f16(acc[mm][g*2+1], a[mm], &bf[2]);
                }
            }
        }
        __syncthreads();
    }

    const float* b1B = g_b1 + b*O1;
    const float* deB = g_de + (long long)b*PS;
    __half* yB = g_yh + (long long)b*PS;
    float* rgB = g_rg + (long long)b*PS;
    int r0 = n0 + warpR * 32 + (lane >> 2);
    int co = warpC * 64 + 2 * (lane & 3);
    #pragma unroll
    for (int mm = 0; mm < 2; mm++)
        #pragma unroll
        for (int nn = 0; nn < 8; nn++) {
            int o = co + nn*8;
            float bb0 = b1B[o], bb1 = b1B[o+1];
            #pragma unroll
            for (int half_ = 0; half_ < 2; half_++) {
                int r = r0 + mm*16 + half_*8;
                float s0 = 1.f/(1.f + expf(-(acc[mm][nn][half_*2+0] + bb0)));
                float s1 = 1.f/(1.f + expf(-(acc[mm][nn][half_*2+1] + bb1)));
                if (warpC == 0) {
                    float2 d = *(const float2*)(deB + (long long)r*HH + o);
                    *(__half2*)(yB + (long long)r*HH + o) = __floats2half2_rn(s0*d.x, s1*d.y);
                } else {
                    *(float2*)(rgB + (long long)r*HH + (o-64)) = make_float2(s0, s1);
                }
            }
        }
}

// ======== gcn2 (fp16 mma): hc = tanh(.), GRU state, time projection =======
__global__ void __launch_bounds__(256) k_gcn2_mma(const float* __restrict__ ow,
                                                  const float* __restrict__ ob,
                                                  float* __restrict__ dout) {
    __shared__ __align__(16) union {
        struct { __half As[128][40]; __half Ws[32][72]; } ld;
        float st[128][65];
    } sm;
    int tid = threadIdx.x;
    int wid = tid >> 5, lane = tid & 31;
    int warpR = wid >> 1, warpC = wid & 1;
    int n0 = blockIdx.x * 128;
    int b  = blockIdx.y;
    const __half* srcs[3] = { g_yh + (long long)b*PS, g_p1h + (long long)b*PS, g_p2h + (long long)b*PS };
    const __half* WB = g_W2h + (long long)b*3*65*O2;

    float acc[2][4][4];
    #pragma unroll
    for (int mm=0;mm<2;mm++)
        #pragma unroll
        for (int nn=0;nn<4;nn++)
            #pragma unroll
            for (int q=0;q<4;q++) acc[mm][nn][q] = 0.f;

    int lrow = lane & 15, lcol = (lane >> 4) << 3;

    for (int kc = 0; kc < 6; kc++) {
        int k = kc >> 1, c0 = (kc & 1) * 32;
        const __half* S = srcs[k];
        #pragma unroll
        for (int it = 0; it < 2; it++) {
            int idx = tid + it * 256;
            int r = idx >> 2, f = idx & 3;
            *(uint4*)&sm.ld.As[r][f*8] = *(const uint4*)(S + (long long)(n0+r)*HH + c0 + f*8);
        }
        {
            int j = tid >> 3, f = tid & 7;
            *(uint4*)&sm.ld.Ws[j][f*8] = *(const uint4*)(WB + (long long)(k*65 + 1 + c0 + j)*O2 + f*8);
        }
        __syncthreads();
        #pragma unroll
        for (int k16 = 0; k16 < 2; k16++) {
            uint32_t a[2][4], bf[2][4];
            #pragma unroll
            for (int mm = 0; mm < 2; mm++)
                ldsm_x4(a[mm], s2u(&sm.ld.As[warpR*32 + mm*16 + lrow][k16*16 + lcol]));
            #pragma unroll
            for (int g = 0; g < 2; g++)
                ldsm_x4_t(bf[g], s2u(&sm.ld.Ws[k16*16 + lrow][warpC*32 + g*16 + lcol]));
            #pragma unroll
            for (int mm = 0; mm < 2; mm++)
                #pragma unroll
                for (int g = 0; g < 2; g++) {
                    mma_f16(acc[mm][g*2+0], a[mm], &bf[g][0]);
                    mma_f16(acc[mm][g*2+1], a[mm], &bf[g][2]);
                }
        }
        __syncthreads();
    }

    const float* b2B = g_b2 + b*O2;
    const float* deB = g_de + (long long)b*PS;
    const float* rgB = g_rg + (long long)b*PS;
    int r0l = warpR * 32 + (lane >> 2);
    int co = warpC * 32 + 2 * (lane & 3);
    #pragma unroll
    for (int mm = 0; mm < 2; mm++)
        #pragma unroll
        for (int nn = 0; nn < 4; nn++) {
            int o = co + nn*8;
            float bb0 = b2B[o], bb1 = b2B[o+1];
            #pragma unroll
            for (int half_ = 0; half_ < 2; half_++) {
                int rl = r0l + mm*16 + half_*8;
                int n = n0 + rl;
                float h0 = tanhf(acc[mm][nn][half_*2+0] + bb0);
                float h1 = tanhf(acc[mm][nn][half_*2+1] + bb1);
                float2 rr = *(const float2*)(rgB + (long long)n*HH + o);
                float2 dd = *(const float2*)(deB + (long long)n*HH + o);
                sm.st[rl][o]   = rr.x*dd.x + (1.f - rr.x)*h0;
                sm.st[rl][o+1] = rr.y*dd.y + (1.f - rr.y)*h1;
            }
        }
    __syncthreads();

    int t = b % 12, bo = b / 12;
    if (tid < 128) {
        int nl = tid;
        float a = ob[t];
        #pragma unroll
        for (int h = 0; h < 64; h++) a = fmaf(sm.st[nl][h], ow[t*64+h], a);
        dout[(long long)bo*TT*NN + t*NN + n0 + nl] = a;
    }
}

// -------------------------------------------------------------------------
extern "C" void kernel_launch(void* const* d_in, const int* in_sizes, int n_in,
                              void* d_out, int out_size) {
    const float* hn  = (const float*)d_in[2];
    const float* ne1 = (const float*)d_in[3];
    const float* ne2 = (const float*)d_in[4];
    const float* E   = (const float*)d_in[5];
    const float* Wq  = (const float*)d_in[6];
    const float* bq  = (const float*)d_in[7];
    const float* Wk  = (const float*)d_in[8];
    const float* bk  = (const float*)d_in[9];
    const float* Wv  = (const float*)d_in[10];
    const float* bv  = (const float*)d_in[11];
    const float* taw = (const float*)d_in[12];
    const float* tab = (const float*)d_in[13];
    const float* gwp = (const float*)d_in[14];
    const float* gw  = (const float*)d_in[15];
    const float* gbp = (const float*)d_in[16];
    const float* gb  = (const float*)d_in[17];
    const float* uwp = (const float*)d_in[18];
    const float* uw  = (const float*)d_in[19];
    const float* ubp = (const float*)d_in[20];
    const float* ub  = (const float*)d_in[21];
    const float* ow  = (const float*)d_in[22];
    const float* ob  = (const float*)d_in[23];
    float* out = (float*)d_out;

    dim3 gprop(8, BT);         // merged [A; 2A^2-I] propagation
    dim3 ggcn (NN/128, BT);

    k_adj<<<512, 512>>>(E);
    k_a2<<<dim3(4, 4), 256>>>();
    k_attn_pre<<<BB, 64>>>(ne1, ne2, Wq, bq, Wk, bk, Wv, bv);
    k_attn2<<<dim3(NN, BB), 128>>>(hn, Wq, Wk, Wv, taw, tab);
    k_wgemm<<<dim3((3*65*O1)/64, BT/64), 256>>>(ne2, gwp, gw, 0);
    k_wgemm<<<dim3((3*65*O2)/64, BT/64), 256>>>(ne2, uwp, uw, 1);
    k_wgemm<<<dim3(O1/64, BT/64), 256>>>(ne2, gbp, gb, 2);
    k_wgemm<<<dim3(O2/64, BT/64), 256>>>(ne2, ubp, ub, 3);
    k_prop2<<<gprop, 256>>>(1);      // p1h, p2h from deh
    k_gcn1_mma<<<ggcn, 256>>>();     // -> yh, rg
    k_prop2<<<gprop, 256>>>(2);      // p1h, p2h from yh
    k_gcn2_mma<<<ggcn, 256>>>(ow, ob, out);
}

// round 13
// speedup vs baseline: 5.3134x; 1.0551x over previous
#include <cuda_runtime.h>
#include <cuda_fp16.h>
#include <cstdint>
#include <math.h>

#define BB 64
#define TT 12
#define BT 768          // BB*TT
#define NN 512
#define HH 64
#define TDD 32
#define O1 128
#define O2 64
#define PS (NN*HH)      // per-slice elements

// ---------------- scratch (device globals; no allocation) ----------------
__device__ __half g_Acat[2*NN*NN];            // rows 0..511: A, rows 512..1023: 2A^2-I
__device__ float  g_de [BT*NN*HH];            // de_input (f32, for GRU epilogues)
__device__ __half g_deh[BT*NN*HH];            // de_input, half (mma operand)
__device__ __half g_yh [BT*NN*HH];            // y = z*de, half
__device__ float  g_rg [BT*NN*HH];            // reset gate (f32)
__device__ __half g_p1h[BT*NN*HH];            // A @ x, half
__device__ __half g_p2h[BT*NN*HH];            // (2A^2-I) @ x, half
__device__ __half g_W1h[BT*3*65*O1];          // per-(b,t) gcn1 weights, half
__device__ __half g_W2h[BT*3*65*O2];          // per-(b,t) gcn2 weights, half
__device__ float  g_b1[BT*O1];
__device__ float  g_b2[BT*O2];
__device__ float  g_spk[BB*64];               // per-b k bias part
__device__ float  g_spv[BB*64];               // per-b v bias part
__device__ float  g_sqq[BB*TT*64];            // per-(b,t) q bias part

// ---------------- mma/ldmatrix/cp.async helpers (sm_80 PTX) ---------------
__device__ __forceinline__ uint32_t s2u(const void* p) {
    return (uint32_t)__cvta_generic_to_shared(p);
}
__device__ __forceinline__ void ldsm_x4(uint32_t* r, uint32_t a) {
    asm volatile("ldmatrix.sync.aligned.m8n8.x4.shared.b16 {%0,%1,%2,%3}, [%4];"
        : "=r"(r[0]), "=r"(r[1]), "=r"(r[2]), "=r"(r[3]) : "r"(a));
}
__device__ __forceinline__ void ldsm_x4_t(uint32_t* r, uint32_t a) {
    asm volatile("ldmatrix.sync.aligned.m8n8.x4.trans.shared.b16 {%0,%1,%2,%3}, [%4];"
        : "=r"(r[0]), "=r"(r[1]), "=r"(r[2]), "=r"(r[3]) : "r"(a));
}
__device__ __forceinline__ void mma_f16(float* c, const uint32_t* a, const uint32_t* b) {
    asm volatile(
        "mma.sync.aligned.m16n8k16.row.col.f32.f16.f16.f32 "
        "{%0,%1,%2,%3}, {%4,%5,%6,%7}, {%8,%9}, {%0,%1,%2,%3};"
        : "+f"(c[0]), "+f"(c[1]), "+f"(c[2]), "+f"(c[3])
        : "r"(a[0]), "r"(a[1]), "r"(a[2]), "r"(a[3]), "r"(b[0]), "r"(b[1]));
}
__device__ __forceinline__ void cp16(void* s, const void* g) {
    asm volatile("cp.async.ca.shared.global [%0], [%1], 16;" :: "r"(s2u(s)), "l"(g));
}
__device__ __forceinline__ void cp_commit() { asm volatile("cp.async.commit_group;"); }
__device__ __forceinline__ void cp_wait1()  { asm volatile("cp.async.wait_group 1;"); }
__device__ __forceinline__ void cp_wait0()  { asm volatile("cp.async.wait_group 0;"); }

// ---------------- adjacency: A = softmax_row(relu(E E^T)) -> half ---------
__global__ void k_adj(const float* __restrict__ E) {
    int n = blockIdx.x;
    int m = threadIdx.x;               // 512 threads
    __shared__ float en[16];
    __shared__ float red[512];
    if (m < 16) en[m] = E[n*16 + m];
    __syncthreads();
    float s = 0.f;
    #pragma unroll
    for (int j = 0; j < 16; j++) s = fmaf(en[j], E[m*16 + j], s);
    s = fmaxf(s, 0.f);
    red[m] = s; __syncthreads();
    for (int off = 256; off > 0; off >>= 1) {
        if (m < off) red[m] = fmaxf(red[m], red[m+off]);
        __syncthreads();
    }
    float mx = red[0]; __syncthreads();
    float e = expf(s - mx);
    red[m] = e; __syncthreads();
    for (int off = 256; off > 0; off >>= 1) {
        if (m < off) red[m] += red[m+off];
        __syncthreads();
    }
    g_Acat[n*NN + m] = __float2half_rn(e / red[0]);
}

// ---------------- A2' = 2*A@A - I  (fp16 mma, rows 512..1023 of Acat) -----
__global__ void __launch_bounds__(256) k_a2() {
    __shared__ __align__(16) __half As[128][40];
    __shared__ __align__(16) __half Bs[32][136];
    int tid = threadIdx.x;
    int wid = tid >> 5, lane = tid & 31;
    int warpR = wid >> 1, warpC = wid & 1;
    int n0 = blockIdx.x * 128;
    int m0 = blockIdx.y * 128;

    float acc[2][8][4];
    #pragma unroll
    for (int mm=0;mm<2;mm++)
        #pragma unroll
        for (int nn=0;nn<8;nn++)
            #pragma unroll
            for (int q=0;q<4;q++) acc[mm][nn][q] = 0.f;

    int lrow = lane & 15, lcol = (lane >> 4) << 3;

    for (int kc = 0; kc < 16; kc++) {
        #pragma unroll
        for (int it = 0; it < 2; it++) {
            int idx = tid + it * 256;
            int r = idx >> 2, f = idx & 3;
            *(uint4*)&As[r][f*8] = *(const uint4*)(g_Acat + (long long)(m0+r)*NN + kc*32 + f*8);
        }
        #pragma unroll
        for (int it = 0; it < 2; it++) {
            int idx = tid + it * 256;
            int j = idx >> 4, f = idx & 15;
            *(uint4*)&Bs[j][f*8] = *(const uint4*)(g_Acat + (long long)(kc*32+j)*NN + n0 + f*8);
        }
        __syncthreads();
        #pragma unroll
        for (int k16 = 0; k16 < 2; k16++) {
            uint32_t a[2][4];
            #pragma unroll
            for (int mm = 0; mm < 2; mm++)
                ldsm_x4(a[mm], s2u(&As[warpR*32 + mm*16 + lrow][k16*16 + lcol]));
            #pragma unroll
            for (int g = 0; g < 4; g++) {
                uint32_t bf[4];
                ldsm_x4_t(bf, s2u(&Bs[k16*16 + lrow][warpC*64 + g*16 + lcol]));
                #pragma unroll
                for (int mm = 0; mm < 2; mm++) {
                    mma_f16(acc[mm][g*2+0], a[mm], &bf[0]);
                    mma_f16(acc[mm][g*2+1], a[mm], &bf[2]);
                }
            }
        }
        __syncthreads();
    }

    int r0 = m0 + warpR * 32 + (lane >> 2);
    int co = n0 + warpC * 64 + 2 * (lane & 3);
    #pragma unroll
    for (int mm = 0; mm < 2; mm++)
        #pragma unroll
        for (int nn = 0; nn < 8; nn++) {
            int c = co + nn*8;
            #pragma unroll
            for (int half_ = 0; half_ < 2; half_++) {
                int r = r0 + mm*16 + half_*8;
                float v0 = 2.f*acc[mm][nn][half_*2+0] - (r == c   ? 1.f : 0.f);
                float v1 = 2.f*acc[mm][nn][half_*2+1] - (r == c+1 ? 1.f : 0.f);
                *(__half2*)(g_Acat + (long long)(NN + r)*NN + c) = __floats2half2_rn(v0, v1);
            }
        }
}

// ======= merged propagation, 2 slices per CTA: [p1;p2] = [A;2A^2-I] @ X ===
__global__ void __launch_bounds__(256) k_prop2(int mode) {
    const __half* X = (mode == 1) ? g_deh : g_yh;
    __half* Y = (blockIdx.x < 4) ? g_p1h : g_p2h;
    int arow0 = blockIdx.x * 128;
    int n0 = (blockIdx.x & 3) * 128;

    __shared__ __align__(16) __half As[2][128][40];
    __shared__ __align__(16) __half Xs[2][2][32][72];   // [buf][slice]

    int tid = threadIdx.x;
    int wid = tid >> 5, lane = tid & 31;
    int warpR = wid >> 1, warpC = wid & 1;
    long long p0 = (long long)blockIdx.y * 2;
    const __half* Xp[2] = { X + p0*PS, X + (p0+1)*PS };
    __half*       Yp[2] = { Y + p0*PS, Y + (p0+1)*PS };

    float acc[2][2][4][4];
    #pragma unroll
    for (int s=0;s<2;s++)
        #pragma unroll
        for (int mm=0;mm<2;mm++)
            #pragma unroll
            for (int nn=0;nn<4;nn++)
                #pragma unroll
                for (int q=0;q<4;q++) acc[s][mm][nn][q] = 0.f;

    int lrow = lane & 15, lcol = (lane >> 4) << 3;

    auto stage = [&](int kc, int buf) {
        #pragma unroll
        for (int it = 0; it < 2; it++) {
            int idx = tid + it * 256;
            int r = idx >> 2, f = idx & 3;
            cp16(&As[buf][r][f*8], g_Acat + (long long)(arow0+r)*NN + kc*32 + f*8);
        }
        #pragma unroll
        for (int s = 0; s < 2; s++) {
            int k = tid >> 3, f = tid & 7;
            cp16(&Xs[buf][s][k][f*8], Xp[s] + (long long)(kc*32 + k)*HH + f*8);
        }
        cp_commit();
    };

    stage(0, 0);
    for (int kc = 0; kc < 16; kc++) {
        int buf = kc & 1;
        if (kc < 15) stage(kc+1, buf ^ 1);
        if (kc < 15) cp_wait1(); else cp_wait0();
        __syncthreads();

        #pragma unroll
        for (int k16 = 0; k16 < 2; k16++) {
            uint32_t a[2][4];
            #pragma unroll
            for (int mm = 0; mm < 2; mm++)
                ldsm_x4(a[mm], s2u(&As[buf][warpR*32 + mm*16 + lrow][k16*16 + lcol]));
            #pragma unroll
            for (int s = 0; s < 2; s++) {
                uint32_t bf[2][4];
                #pragma unroll
                for (int g = 0; g < 2; g++)
                    ldsm_x4_t(bf[g], s2u(&Xs[buf][s][k16*16 + lrow][warpC*32 + g*16 + lcol]));
                #pragma unroll
                for (int mm = 0; mm < 2; mm++)
                    #pragma unroll
                    for (int g = 0; g < 2; g++) {
                        mma_f16(acc[s][mm][g*2+0], a[mm], &bf[g][0]);
                        mma_f16(acc[s][mm][g*2+1], a[mm], &bf[g][2]);
                    }
            }
        }
        __syncthreads();
    }

    int r0 = n0 + warpR * 32 + (lane >> 2);
    int c0 = warpC * 32 + 2 * (lane & 3);
    #pragma unroll
    for (int s = 0; s < 2; s++)
        #pragma unroll
        for (int mm = 0; mm < 2; mm++)
            #pragma unroll
            for (int nn = 0; nn < 4; nn++) {
                int r = r0 + mm*16, c = c0 + nn*8;
                *(__half2*)(Yp[s] + (long long)r*HH + c) =
                    __floats2half2_rn(acc[s][mm][nn][0], acc[s][mm][nn][1]);
                *(__half2*)(Yp[s] + (long long)(r+8)*HH + c) =
                    __floats2half2_rn(acc[s][mm][nn][2], acc[s][mm][nn][3]);
            }
}

// ---------------- attention prelude: per-b / per-(b,t) bias parts --------
__global__ void k_attn_pre(const float* __restrict__ ne1, const float* __restrict__ ne2,
                           const float* __restrict__ Wq, const float* __restrict__ bq,
                           const float* __restrict__ Wk, const float* __restrict__ bk,
                           const float* __restrict__ Wv, const float* __restrict__ bv) {
    int b = blockIdx.x;
    int h = threadIdx.x;               // 64 threads
    __shared__ float sp[32], sq[TT*TDD];
    if (h < 32) sp[h] = ne1[b*TT*TDD + 11*TDD + h];
    for (int i = h; i < TT*TDD; i += 64) sq[i] = ne2[b*TT*TDD + i];
    __syncthreads();
    float ak = bk[h], av = bv[h];
    #pragma unroll
    for (int j = 0; j < 32; j++) {
        ak = fmaf(sp[j], Wk[j*64+h], ak);
        av = fmaf(sp[j], Wv[j*64+h], av);
    }
    g_spk[b*64+h] = ak;
    g_spv[b*64+h] = av;
    #pragma unroll
    for (int t = 0; t < TT; t++) {
        float a = bq[h];
        #pragma unroll
        for (int j = 0; j < 32; j++) a = fmaf(sq[t*32+j], Wq[j*64+h], a);
        g_sqq[(b*TT+t)*64+h] = a;
    }
}

// ------- temporal attention main (rank-8, round-8 known-good) ------------
__global__ void k_attn2(const float* __restrict__ hn,
                        const float* __restrict__ Wq, const float* __restrict__ Wk,
                        const float* __restrict__ Wv,
                        const float* __restrict__ taw, const float* __restrict__ tab) {
    int n = blockIdx.x, b = blockIdx.y;
    int tid = threadIdx.x;             // 128
    __shared__ float xs[64], ks[64], vs[64], xq[64], t1[64], lg[96], us[8][64], sqs[TT*64];

    if (tid < 64) xs[tid] = hn[((long long)b*NN + n)*HH + tid];
    for (int i = tid; i < TT*64; i += 128) sqs[i] = g_sqq[b*TT*64 + i];
    __syncthreads();

    {
        int h = tid & 63;
        if (tid < 64) {
            float a = g_spk[b*64+h], a2 = 0.f;
            #pragma unroll
            for (int j = 0; j < 64; j++) {
                a  = fmaf(xs[j], Wk[(32+j)*64+h], a);
                a2 = fmaf(xs[j], Wq[(32+j)*64+h], a2);
            }
            ks[h] = fmaxf(a, 0.f);
            xq[h] = a2;
        } else {
            float a = g_spv[b*64+h], a2 = tab[h];
            #pragma unroll
            for (int j = 0; j < 64; j++) {
                a  = fmaf(xs[j], Wv[(32+j)*64+h], a);
                a2 = fmaf(xs[j], taw[j*64+h], a2);
            }
            vs[h] = fmaxf(a, 0.f);
            t1[h] = a2;
        }
    }
    __syncthreads();
    if (tid < 96) {                    // logits per (head d, time t)
        int d = tid / 12, t = tid % 12;
        float a = 0.f;
        #pragma unroll
        for (int c = 0; c < 8; c++) {
            int h = d*8 + c;
            float q = fmaxf(xq[h] + sqs[t*64+h], 0.f);
            a = fmaf(q, ks[h], a);
        }
        lg[d*12+t] = a;
    }
    __syncthreads();
    if (tid < 8) {                     // softmax over t
        int d = tid;
        float mx = -1e30f;
        for (int t = 0; t < 12; t++) mx = fmaxf(mx, lg[d*12+t]);
        float s = 0.f;
        for (int t = 0; t < 12; t++) { float e = expf(lg[d*12+t]-mx); lg[d*12+t] = e; s += e; }
        float inv = 1.f/s;
        for (int t = 0; t < 12; t++) lg[d*12+t] *= inv;
    }
    __syncthreads();
    for (int idx = tid; idx < 512; idx += 128) {    // us[d][h] = sum_i vs[i]*taw2[i][h]
        int d = idx >> 6, h = idx & 63;
        float a = 0.f;
        #pragma unroll
        for (int c = 0; c < 8; c++) {
            int i = d*8 + c;
            a = fmaf(vs[i], taw[4096 + i*64 + h], a);
        }
        us[d][h] = a;
    }
    __syncthreads();
    for (int idx = tid; idx < TT*64; idx += 128) {
        int t = idx >> 6, h = idx & 63;
        float a = t1[h];
        #pragma unroll
        for (int d = 0; d < 8; d++) a = fmaf(lg[d*12+t], us[d][h], a);
        long long o = ((long long)(b*12+t)*NN + n)*HH + h;
        g_de[o]  = a;
        g_deh[o] = __float2half_rn(a);
    }
}

// ---- per-(b,t) weights (round-8 scalar, known good): temb@B + bias -------
// mode 0: gwp->g_W1h  1: uwp->g_W2h  2: gbp->g_b1  3: ubp->g_b2
__global__ void k_wgemm(const float* __restrict__ Am, const float* __restrict__ Bm,
                        const float* __restrict__ bias, int mode) {
    __half* Ch = nullptr; float* Cf = nullptr; int Nc;
    if (mode == 0)      { Ch = g_W1h; Nc = 3*65*O1; }
    else if (mode == 1) { Ch = g_W2h; Nc = 3*65*O2; }
    else if (mode == 2) { Cf = g_b1; Nc = O1; }
    else                { Cf = g_b2; Nc = O2; }

    __shared__ float At[32][65];
    __shared__ float Bt[32][64];
    int q0 = blockIdx.x * 64;
    int m0 = blockIdx.y * 64;
    int tid = threadIdx.x;
    int tx = tid & 15, ty = tid >> 4;
    #pragma unroll
    for (int p=0;p<8;p++) {
        int idx = tid + p*256;
        int d = idx & 31, m = idx >> 5;
        At[d][m] = Am[(m0+m)*32 + d];
    }
    #pragma unroll
    for (int p=0;p<8;p++) {
        int idx = tid + p*256;
        int q = idx & 63, d = idx >> 6;
        Bt[d][q] = Bm[(long long)d*Nc + q0 + q];
    }
    __syncthreads();
    float acc[4][4] = {};
    #pragma unroll
    for (int d=0; d<32; d++) {
        float a[4];
        #pragma unroll
        for (int i=0;i<4;i++) a[i] = At[d][ty*4+i];
        float4 b4 = *(const float4*)&Bt[d][tx*4];
        float bv[4] = {b4.x,b4.y,b4.z,b4.w};
        #pragma unroll
        for (int i=0;i<4;i++)
            #pragma unroll
            for (int j=0;j<4;j++) acc[i][j] = fmaf(a[i], bv[j], acc[i][j]);
    }
    float4 bb = *(const float4*)&bias[q0 + tx*4];
    float bs[4] = {bb.x,bb.y,bb.z,bb.w};
    #pragma unroll
    for (int i=0;i<4;i++) {
        float v0 = acc[i][0]+bs[0], v1 = acc[i][1]+bs[1];
        float v2 = acc[i][2]+bs[2], v3 = acc[i][3]+bs[3];
        long long off = (long long)(m0+ty*4+i)*Nc + q0 + tx*4;
        if (Ch) {
            *(__half2*)(Ch + off)     = __floats2half2_rn(v0, v1);
            *(__half2*)(Ch + off + 2) = __floats2half2_rn(v2, v3);
        } else {
            *(float4*)(Cf + off) = make_float4(v0, v1, v2, v3);
        }
    }
}

// ======== gcn1 (fp16 mma): zr = sigmoid(xg@W1+b1) -> yh = z*de, rg ========
__global__ void __launch_bounds__(256) k_gcn1_mma() {
    __shared__ __align__(16) __half As[128][40];
    __shared__ __align__(16) __half Ws[32][136];
    int tid = threadIdx.x;
    int wid = tid >> 5, lane = tid & 31;
    int warpR = wid >> 1, warpC = wid & 1;
    int n0 = blockIdx.x * 128;
    int b  = blockIdx.y;
    const __half* srcs[3] = { g_deh + (long long)b*PS, g_p1h + (long long)b*PS, g_p2h + (long long)b*PS };
    const __half* WB = g_W1h + (long long)b*3*65*O1;

    float acc[2][8][4];
    #pragma unroll
    for (int mm=0;mm<2;mm++)
        #pragma unroll
        for (int nn=0;nn<8;nn++)
            #pragma unroll
            for (int q=0;q<4;q++) acc[mm][nn][q] = 0.f;

    int lrow = lane & 15, lcol = (lane >> 4) << 3;

    for (int kc = 0; kc < 6; kc++) {
        int k = kc >> 1, c0 = (kc & 1) * 32;
        const __half* S = srcs[k];
        #pragma unroll
        for (int it = 0; it < 2; it++) {
            int idx = tid + it * 256;
            int r = idx >> 2, f = idx & 3;
            *(uint4*)&As[r][f*8] = *(const uint4*)(S + (long long)(n0+r)*HH + c0 + f*8);
        }
        #pragma unroll
        for (int it = 0; it < 2; it++) {
            int idx = tid + it * 256;
            int j = idx >> 4, f = idx & 15;
            *(uint4*)&Ws[j][f*8] = *(const uint4*)(WB + (long long)(k*65 + 1 + c0 + j)*O1 + f*8);
        }
        __syncthreads();
        #pragma unroll
        for (int k16 = 0; k16 < 2; k16++) {
            uint32_t a[2][4];
            #pragma unroll
            for (int mm = 0; mm < 2; mm++)
                ldsm_x4(a[mm], s2u(&As[warpR*32 + mm*16 + lrow][k16*16 + lcol]));
            #pragma unroll
            for (int g = 0; g < 4; g++) {
                uint32_t bf[4];
                ldsm_x4_t(bf, s2u(&Ws[k16*16 + lrow][warpC*64 + g*16 + lcol]));
                #pragma unroll
                for (int mm = 0; mm < 2; mm++) {
                    mma_f16(acc[mm][g*2+0], a[mm], &bf[0]);
                    mma_f16(acc[mm][g*2+1], a[mm], &bf[2]);
                }
            }
        }
        __syncthreads();
    }

    const float* b1B = g_b1 + b*O1;
    const float* deB = g_de + (long long)b*PS;
    __half* yB = g_yh + (long long)b*PS;
    float* rgB = g_rg + (long long)b*PS;
    int r0 = n0 + warpR * 32 + (lane >> 2);
    int co = warpC * 64 + 2 * (lane & 3);
    #pragma unroll
    for (int mm = 0; mm < 2; mm++)
        #pragma unroll
        for (int nn = 0; nn < 8; nn++) {
            int o = co + nn*8;
            float bb0 = b1B[o], bb1 = b1B[o+1];
            #pragma unroll
            for (int half_ = 0; half_ < 2; half_++) {
                int r = r0 + mm*16 + half_*8;
                float s0 = 1.f/(1.f + expf(-(acc[mm][nn][half_*2+0] + bb0)));
                float s1 = 1.f/(1.f + expf(-(acc[mm][nn][half_*2+1] + bb1)));
                if (warpC == 0) {
                    float2 d = *(const float2*)(deB + (long long)r*HH + o);
                    *(__half2*)(yB + (long long)r*HH + o) = __floats2half2_rn(s0*d.x, s1*d.y);
                } else {
                    *(float2*)(rgB + (long long)r*HH + (o-64)) = make_float2(s0, s1);
                }
            }
        }
}

// ======== gcn2 (fp16 mma): hc = tanh(.), GRU state, time projection =======
__global__ void __launch_bounds__(256) k_gcn2_mma(const float* __restrict__ ow,
                                                  const float* __restrict__ ob,
                                                  float* __restrict__ dout) {
    __shared__ __align__(16) union {
        struct { __half As[128][40]; __half Ws[32][72]; } ld;
        float st[128][65];
    } sm;
    int tid = threadIdx.x;
    int wid = tid >> 5, lane = tid & 31;
    int warpR = wid >> 1, warpC = wid & 1;
    int n0 = blockIdx.x * 128;
    int b  = blockIdx.y;
    const __half* srcs[3] = { g_yh + (long long)b*PS, g_p1h + (long long)b*PS, g_p2h + (long long)b*PS };
    const __half* WB = g_W2h + (long long)b*3*65*O2;

    float acc[2][4][4];
    #pragma unroll
    for (int mm=0;mm<2;mm++)
        #pragma unroll
        for (int nn=0;nn<4;nn++)
            #pragma unroll
            for (int q=0;q<4;q++) acc[mm][nn][q] = 0.f;

    int lrow = lane & 15, lcol = (lane >> 4) << 3;

    for (int kc = 0; kc < 6; kc++) {
        int k = kc >> 1, c0 = (kc & 1) * 32;
        const __half* S = srcs[k];
        #pragma unroll
        for (int it = 0; it < 2; it++) {
            int idx = tid + it * 256;
            int r = idx >> 2, f = idx & 3;
            *(uint4*)&sm.ld.As[r][f*8] = *(const uint4*)(S + (long long)(n0+r)*HH + c0 + f*8);
        }
        {
            int j = tid >> 3, f = tid & 7;
            *(uint4*)&sm.ld.Ws[j][f*8] = *(const uint4*)(WB + (long long)(k*65 + 1 + c0 + j)*O2 + f*8);
        }
        __syncthreads();
        #pragma unroll
        for (int k16 = 0; k16 < 2; k16++) {
            uint32_t a[2][4], bf[2][4];
            #pragma unroll
            for (int mm = 0; mm < 2; mm++)
                ldsm_x4(a[mm], s2u(&sm.ld.As[warpR*32 + mm*16 + lrow][k16*16 + lcol]));
            #pragma unroll
            for (int g = 0; g < 2; g++)
                ldsm_x4_t(bf[g], s2u(&sm.ld.Ws[k16*16 + lrow][warpC*32 + g*16 + lcol]));
            #pragma unroll
            for (int mm = 0; mm < 2; mm++)
                #pragma unroll
                for (int g = 0; g < 2; g++) {
                    mma_f16(acc[mm][g*2+0], a[mm], &bf[g][0]);
                    mma_f16(acc[mm][g*2+1], a[mm], &bf[g][2]);
                }
        }
        __syncthreads();
    }

    const float* b2B = g_b2 + b*O2;
    const float* deB = g_de + (long long)b*PS;
    const float* rgB = g_rg + (long long)b*PS;
    int r0l = warpR * 32 + (lane >> 2);
    int co = warpC * 32 + 2 * (lane & 3);
    #pragma unroll
    for (int mm = 0; mm < 2; mm++)
        #pragma unroll
        for (int nn = 0; nn < 4; nn++) {
            int o = co + nn*8;
            float bb0 = b2B[o], bb1 = b2B[o+1];
            #pragma unroll
            for (int half_ = 0; half_ < 2; half_++) {
                int rl = r0l + mm*16 + half_*8;
                int n = n0 + rl;
                float h0 = tanhf(acc[mm][nn][half_*2+0] + bb0);
                float h1 = tanhf(acc[mm][nn][half_*2+1] + bb1);
                float2 rr = *(const float2*)(rgB + (long long)n*HH + o);
                float2 dd = *(const float2*)(deB + (long long)n*HH + o);
                sm.st[rl][o]   = rr.x*dd.x + (1.f - rr.x)*h0;
                sm.st[rl][o+1] = rr.y*dd.y + (1.f - rr.y)*h1;
            }
        }
    __syncthreads();

    int t = b % 12, bo = b / 12;
    if (tid < 128) {
        int nl = tid;
        float a = ob[t];
        #pragma unroll
        for (int h = 0; h < 64; h++) a = fmaf(sm.st[nl][h], ow[t*64+h], a);
        dout[(long long)bo*TT*NN + t*NN + n0 + nl] = a;
    }
}

// -------------------------------------------------------------------------
extern "C" void kernel_launch(void* const* d_in, const int* in_sizes, int n_in,
                              void* d_out, int out_size) {
    const float* hn  = (const float*)d_in[2];
    const float* ne1 = (const float*)d_in[3];
    const float* ne2 = (const float*)d_in[4];
    const float* E   = (const float*)d_in[5];
    const float* Wq  = (const float*)d_in[6];
    const float* bq  = (const float*)d_in[7];
    const float* Wk  = (const float*)d_in[8];
    const float* bk  = (const float*)d_in[9];
    const float* Wv  = (const float*)d_in[10];
    const float* bv  = (const float*)d_in[11];
    const float* taw = (const float*)d_in[12];
    const float* tab = (const float*)d_in[13];
    const float* gwp = (const float*)d_in[14];
    const float* gw  = (const float*)d_in[15];
    const float* gbp = (const float*)d_in[16];
    const float* gb  = (const float*)d_in[17];
    const float* uwp = (const float*)d_in[18];
    const float* uw  = (const float*)d_in[19];
    const float* ubp = (const float*)d_in[20];
    const float* ub  = (const float*)d_in[21];
    const float* ow  = (const float*)d_in[22];
    const float* ob  = (const float*)d_in[23];
    float* out = (float*)d_out;

    dim3 gprop(8, BT/2);       // 2 slices per CTA
    dim3 ggcn (NN/128, BT);

    k_adj<<<512, 512>>>(E);                                                 // 1
    k_a2<<<dim3(4, 4), 256>>>();                                            // 2
    k_attn_pre<<<BB, 64>>>(ne1, ne2, Wq, bq, Wk, bk, Wv, bv);               // 3
    k_attn2<<<dim3(NN, BB), 128>>>(hn, Wq, Wk, Wv, taw, tab);               // 4
    k_wgemm<<<dim3((3*65*O1)/64, BT/64), 256>>>(ne2, gwp, gw, 0);           // 5
    k_prop2<<<gprop, 256>>>(1);                                  // profiled 6
    k_wgemm<<<dim3((3*65*O2)/64, BT/64), 256>>>(ne2, uwp, uw, 1);
    k_wgemm<<<dim3(O1/64, BT/64), 256>>>(ne2, gbp, gb, 2);
    k_wgemm<<<dim3(O2/64, BT/64), 256>>>(ne2, ubp, ub, 3);
    k_gcn1_mma<<<ggcn, 256>>>();
    k_prop2<<<gprop, 256>>>(2);
    k_gcn2_mma<<<ggcn, 256>>>(ow, ob, out);
}

// round 14
// speedup vs baseline: 5.5699x; 1.0483x over previous
#include <cuda_runtime.h>
#include <cuda_fp16.h>
#include <cstdint>
#include <math.h>

#define BB 64
#define TT 12
#define BT 768          // BB*TT
#define NN 512
#define HH 64
#define TDD 32
#define O1 128
#define O2 64
#define PS (NN*HH)      // per-slice elements

// ---------------- scratch (device globals; no allocation) ----------------
__device__ __half g_Acat[2*NN*NN];            // rows 0..511: A, rows 512..1023: 2A^2-I
__device__ float  g_de [BT*NN*HH];            // de_input (f32, for GRU epilogues)
__device__ __half g_deh[BT*NN*HH];            // de_input, half (mma operand)
__device__ __half g_yh [BT*NN*HH];            // y = z*de, half
__device__ float  g_rg [BT*NN*HH];            // reset gate (f32)
__device__ __half g_p1h[BT*NN*HH];            // A @ x, half
__device__ __half g_p2h[BT*NN*HH];            // (2A^2-I) @ x, half
__device__ __half g_W1h[BT*3*65*O1];          // per-(b,t) gcn1 weights, half
__device__ __half g_W2h[BT*3*65*O2];          // per-(b,t) gcn2 weights, half
__device__ float  g_b1[BT*O1];
__device__ float  g_b2[BT*O2];
__device__ float  g_spk[BB*64];               // per-b k bias part
__device__ float  g_spv[BB*64];               // per-b v bias part
__device__ float  g_sqq[BB*TT*64];            // per-(b,t) q bias part
__device__ float  g_ks[BB*NN*64];             // relu(X@Wk2 + spk)
__device__ float  g_vs[BB*NN*64];             // relu(X@Wv2 + spv)
__device__ float  g_xq[BB*NN*64];             // X@Wq2
__device__ float  g_t1[BB*NN*64];             // X@taw1 + tab

// ---------------- mma/ldmatrix/cp.async helpers (sm_80 PTX) ---------------
__device__ __forceinline__ uint32_t s2u(const void* p) {
    return (uint32_t)__cvta_generic_to_shared(p);
}
__device__ __forceinline__ void ldsm_x4(uint32_t* r, uint32_t a) {
    asm volatile("ldmatrix.sync.aligned.m8n8.x4.shared.b16 {%0,%1,%2,%3}, [%4];"
        : "=r"(r[0]), "=r"(r[1]), "=r"(r[2]), "=r"(r[3]) : "r"(a));
}
__device__ __forceinline__ void ldsm_x4_t(uint32_t* r, uint32_t a) {
    asm volatile("ldmatrix.sync.aligned.m8n8.x4.trans.shared.b16 {%0,%1,%2,%3}, [%4];"
        : "=r"(r[0]), "=r"(r[1]), "=r"(r[2]), "=r"(r[3]) : "r"(a));
}
__device__ __forceinline__ void mma_f16(float* c, const uint32_t* a, const uint32_t* b) {
    asm volatile(
        "mma.sync.aligned.m16n8k16.row.col.f32.f16.f16.f32 "
        "{%0,%1,%2,%3}, {%4,%5,%6,%7}, {%8,%9}, {%0,%1,%2,%3};"
        : "+f"(c[0]), "+f"(c[1]), "+f"(c[2]), "+f"(c[3])
        : "r"(a[0]), "r"(a[1]), "r"(a[2]), "r"(a[3]), "r"(b[0]), "r"(b[1]));
}
__device__ __forceinline__ void cp16(void* s, const void* g) {
    asm volatile("cp.async.ca.shared.global [%0], [%1], 16;" :: "r"(s2u(s)), "l"(g));
}
__device__ __forceinline__ void cp_commit() { asm volatile("cp.async.commit_group;"); }
__device__ __forceinline__ void cp_wait1()  { asm volatile("cp.async.wait_group 1;"); }
__device__ __forceinline__ void cp_wait0()  { asm volatile("cp.async.wait_group 0;"); }
__device__ __forceinline__ void cvt4(__half* d, float4 v) {
    *(__half2*)(d)   = __floats2half2_rn(v.x, v.y);
    *(__half2*)(d+2) = __floats2half2_rn(v.z, v.w);
}

// ---------------- adjacency: A = softmax_row(relu(E E^T)) -> half ---------
__global__ void k_adj(const float* __restrict__ E) {
    int n = blockIdx.x;
    int m = threadIdx.x;               // 512 threads
    __shared__ float en[16];
    __shared__ float red[512];
    if (m < 16) en[m] = E[n*16 + m];
    __syncthreads();
    float s = 0.f;
    #pragma unroll
    for (int j = 0; j < 16; j++) s = fmaf(en[j], E[m*16 + j], s);
    s = fmaxf(s, 0.f);
    red[m] = s; __syncthreads();
    for (int off = 256; off > 0; off >>= 1) {
        if (m < off) red[m] = fmaxf(red[m], red[m+off]);
        __syncthreads();
    }
    float mx = red[0]; __syncthreads();
    float e = expf(s - mx);
    red[m] = e; __syncthreads();
    for (int off = 256; off > 0; off >>= 1) {
        if (m < off) red[m] += red[m+off];
        __syncthreads();
    }
    g_Acat[n*NN + m] = __float2half_rn(e / red[0]);
}

// ---------------- A2' = 2*A@A - I  (fp16 mma, rows 512..1023 of Acat) -----
__global__ void __launch_bounds__(256) k_a2() {
    __shared__ __align__(16) __half As[128][40];
    __shared__ __align__(16) __half Bs[32][136];
    int tid = threadIdx.x;
    int wid = tid >> 5, lane = tid & 31;
    int warpR = wid >> 1, warpC = wid & 1;
    int n0 = blockIdx.x * 128;
    int m0 = blockIdx.y * 128;

    float acc[2][8][4];
    #pragma unroll
    for (int mm=0;mm<2;mm++)
        #pragma unroll
        for (int nn=0;nn<8;nn++)
            #pragma unroll
            for (int q=0;q<4;q++) acc[mm][nn][q] = 0.f;

    int lrow = lane & 15, lcol = (lane >> 4) << 3;

    for (int kc = 0; kc < 16; kc++) {
        #pragma unroll
        for (int it = 0; it < 2; it++) {
            int idx = tid + it * 256;
            int r = idx >> 2, f = idx & 3;
            *(uint4*)&As[r][f*8] = *(const uint4*)(g_Acat + (long long)(m0+r)*NN + kc*32 + f*8);
        }
        #pragma unroll
        for (int it = 0; it < 2; it++) {
            int idx = tid + it * 256;
            int j = idx >> 4, f = idx & 15;
            *(uint4*)&Bs[j][f*8] = *(const uint4*)(g_Acat + (long long)(kc*32+j)*NN + n0 + f*8);
        }
        __syncthreads();
        #pragma unroll
        for (int k16 = 0; k16 < 2; k16++) {
            uint32_t a[2][4];
            #pragma unroll
            for (int mm = 0; mm < 2; mm++)
                ldsm_x4(a[mm], s2u(&As[warpR*32 + mm*16 + lrow][k16*16 + lcol]));
            #pragma unroll
            for (int g = 0; g < 4; g++) {
                uint32_t bf[4];
                ldsm_x4_t(bf, s2u(&Bs[k16*16 + lrow][warpC*64 + g*16 + lcol]));
                #pragma unroll
                for (int mm = 0; mm < 2; mm++) {
                    mma_f16(acc[mm][g*2+0], a[mm], &bf[0]);
                    mma_f16(acc[mm][g*2+1], a[mm], &bf[2]);
                }
            }
        }
        __syncthreads();
    }

    int r0 = m0 + warpR * 32 + (lane >> 2);
    int co = n0 + warpC * 64 + 2 * (lane & 3);
    #pragma unroll
    for (int mm = 0; mm < 2; mm++)
        #pragma unroll
        for (int nn = 0; nn < 8; nn++) {
            int c = co + nn*8;
            #pragma unroll
            for (int half_ = 0; half_ < 2; half_++) {
                int r = r0 + mm*16 + half_*8;
                float v0 = 2.f*acc[mm][nn][half_*2+0] - (r == c   ? 1.f : 0.f);
                float v1 = 2.f*acc[mm][nn][half_*2+1] - (r == c+1 ? 1.f : 0.f);
                *(__half2*)(g_Acat + (long long)(NN + r)*NN + c) = __floats2half2_rn(v0, v1);
            }
        }
}

// ======= merged propagation, 2 slices per CTA: [p1;p2] = [A;2A^2-I] @ X ===
__global__ void __launch_bounds__(256) k_prop2(int mode) {
    const __half* X = (mode == 1) ? g_deh : g_yh;
    __half* Y = (blockIdx.x < 4) ? g_p1h : g_p2h;
    int arow0 = blockIdx.x * 128;
    int n0 = (blockIdx.x & 3) * 128;

    __shared__ __align__(16) __half As[2][128][40];
    __shared__ __align__(16) __half Xs[2][2][32][72];   // [buf][slice]

    int tid = threadIdx.x;
    int wid = tid >> 5, lane = tid & 31;
    int warpR = wid >> 1, warpC = wid & 1;
    long long p0 = (long long)blockIdx.y * 2;
    const __half* Xp[2] = { X + p0*PS, X + (p0+1)*PS };
    __half*       Yp[2] = { Y + p0*PS, Y + (p0+1)*PS };

    float acc[2][2][4][4];
    #pragma unroll
    for (int s=0;s<2;s++)
        #pragma unroll
        for (int mm=0;mm<2;mm++)
            #pragma unroll
            for (int nn=0;nn<4;nn++)
                #pragma unroll
                for (int q=0;q<4;q++) acc[s][mm][nn][q] = 0.f;

    int lrow = lane & 15, lcol = (lane >> 4) << 3;

    auto stage = [&](int kc, int buf) {
        #pragma unroll
        for (int it = 0; it < 2; it++) {
            int idx = tid + it * 256;
            int r = idx >> 2, f = idx & 3;
            cp16(&As[buf][r][f*8], g_Acat + (long long)(arow0+r)*NN + kc*32 + f*8);
        }
        #pragma unroll
        for (int s = 0; s < 2; s++) {
            int k = tid >> 3, f = tid & 7;
            cp16(&Xs[buf][s][k][f*8], Xp[s] + (long long)(kc*32 + k)*HH + f*8);
        }
        cp_commit();
    };

    stage(0, 0);
    for (int kc = 0; kc < 16; kc++) {
        int buf = kc & 1;
        if (kc < 15) stage(kc+1, buf ^ 1);
        if (kc < 15) cp_wait1(); else cp_wait0();
        __syncthreads();

        #pragma unroll
        for (int k16 = 0; k16 < 2; k16++) {
            uint32_t a[2][4];
            #pragma unroll
            for (int mm = 0; mm < 2; mm++)
                ldsm_x4(a[mm], s2u(&As[buf][warpR*32 + mm*16 + lrow][k16*16 + lcol]));
            #pragma unroll
            for (int s = 0; s < 2; s++) {
                uint32_t bf[2][4];
                #pragma unroll
                for (int g = 0; g < 2; g++)
                    ldsm_x4_t(bf[g], s2u(&Xs[buf][s][k16*16 + lrow][warpC*32 + g*16 + lcol]));
                #pragma unroll
                for (int mm = 0; mm < 2; mm++)
                    #pragma unroll
                    for (int g = 0; g < 2; g++) {
                        mma_f16(acc[s][mm][g*2+0], a[mm], &bf[g][0]);
                        mma_f16(acc[s][mm][g*2+1], a[mm], &bf[g][2]);
                    }
            }
        }
        __syncthreads();
    }

    int r0 = n0 + warpR * 32 + (lane >> 2);
    int c0 = warpC * 32 + 2 * (lane & 3);
    #pragma unroll
    for (int s = 0; s < 2; s++)
        #pragma unroll
        for (int mm = 0; mm < 2; mm++)
            #pragma unroll
            for (int nn = 0; nn < 4; nn++) {
                int r = r0 + mm*16, c = c0 + nn*8;
                *(__half2*)(Yp[s] + (long long)r*HH + c) =
                    __floats2half2_rn(acc[s][mm][nn][0], acc[s][mm][nn][1]);
                *(__half2*)(Yp[s] + (long long)(r+8)*HH + c) =
                    __floats2half2_rn(acc[s][mm][nn][2], acc[s][mm][nn][3]);
            }
}

// ---------------- attention prelude: per-b / per-(b,t) bias parts --------
__global__ void k_attn_pre(const float* __restrict__ ne1, const float* __restrict__ ne2,
                           const float* __restrict__ Wq, const float* __restrict__ bq,
                           const float* __restrict__ Wk, const float* __restrict__ bk,
                           const float* __restrict__ Wv, const float* __restrict__ bv) {
    int b = blockIdx.x;
    int h = threadIdx.x;               // 64 threads
    __shared__ float sp[32], sq[TT*TDD];
    if (h < 32) sp[h] = ne1[b*TT*TDD + 11*TDD + h];
    for (int i = h; i < TT*TDD; i += 64) sq[i] = ne2[b*TT*TDD + i];
    __syncthreads();
    float ak = bk[h], av = bv[h];
    #pragma unroll
    for (int j = 0; j < 32; j++) {
        ak = fmaf(sp[j], Wk[j*64+h], ak);
        av = fmaf(sp[j], Wv[j*64+h], av);
    }
    g_spk[b*64+h] = ak;
    g_spv[b*64+h] = av;
    #pragma unroll
    for (int t = 0; t < TT; t++) {
        float a = bq[h];
        #pragma unroll
        for (int j = 0; j < 32; j++) a = fmaf(sq[t*32+j], Wq[j*64+h], a);
        g_sqq[(b*TT+t)*64+h] = a;
    }
}

// ======== qkv batched GEMM (fp16 mma): per b, X(512x64) @ W'(64x128) ======
// grid (4 m-tiles, 2 pairs, 64 b). pair 0 -> [K|V], pair 1 -> [XQ|T1].
__global__ void __launch_bounds__(256) k_qkv(const float* __restrict__ hn,
                                             const float* __restrict__ Wq,
                                             const float* __restrict__ Wk,
                                             const float* __restrict__ Wv,
                                             const float* __restrict__ taw,
                                             const float* __restrict__ tab) {
    __shared__ __align__(16) __half Xs[128][72];
    __shared__ __align__(16) __half Ws[64][136];
    int tid = threadIdx.x;
    int wid = tid >> 5, lane = tid & 31;
    int warpR = wid >> 1, warpC = wid & 1;
    int n0 = blockIdx.x * 128;
    int pair = blockIdx.y;
    int b = blockIdx.z;

    // X tile: rows = nodes, cols = 64 features (convert f32->half)
    #pragma unroll
    for (int it = 0; it < 8; it++) {
        int idx = tid + it * 256;      // 128 rows x 16 float4
        int r = idx >> 4, f = idx & 15;
        float4 v = *(const float4*)(hn + ((long long)b*NN + n0 + r)*HH + f*4);
        cvt4(&Xs[r][f*4], v);
    }
    // W' tile: 64 rows (features) x 128 cols (two outputs)
    const float* S0 = (pair == 0) ? (Wk + 32*64) : (Wq + 32*64);
    const float* S1 = (pair == 0) ? (Wv + 32*64) : taw;
    #pragma unroll
    for (int it = 0; it < 8; it++) {
        int idx = tid + it * 256;      // 64 rows x 32 float4
        int j = idx >> 5, q = idx & 31;
        int src = q >> 4, f = q & 15;
        float4 v = *(const float4*)((src ? S1 : S0) + j*64 + f*4);
        cvt4(&Ws[j][src*64 + f*4], v);
    }
    __syncthreads();

    int lrow = lane & 15, lcol = (lane >> 4) << 3;
    float acc[2][8][4];
    #pragma unroll
    for (int mm=0;mm<2;mm++)
        #pragma unroll
        for (int nn=0;nn<8;nn++)
            #pragma unroll
            for (int q=0;q<4;q++) acc[mm][nn][q] = 0.f;

    #pragma unroll
    for (int k16 = 0; k16 < 4; k16++) {
        uint32_t a[2][4];
        #pragma unroll
        for (int mm = 0; mm < 2; mm++)
            ldsm_x4(a[mm], s2u(&Xs[warpR*32 + mm*16 + lrow][k16*16 + lcol]));
        #pragma unroll
        for (int g = 0; g < 4; g++) {
            uint32_t bf[4];
            ldsm_x4_t(bf, s2u(&Ws[k16*16 + lrow][warpC*64 + g*16 + lcol]));
            #pragma unroll
            for (int mm = 0; mm < 2; mm++) {
                mma_f16(acc[mm][g*2+0], a[mm], &bf[0]);
                mma_f16(acc[mm][g*2+1], a[mm], &bf[2]);
            }
        }
    }

    int r0 = n0 + warpR * 32 + (lane >> 2);
    int co = warpC * 64 + 2 * (lane & 3);
    #pragma unroll
    for (int mm = 0; mm < 2; mm++)
        #pragma unroll
        for (int nn = 0; nn < 8; nn++) {
            int c = co + nn*8;
            int h = c & 63;
            float* dst; float bb0, bb1; bool rl;
            if (pair == 0) {
                if (c < 64) { dst = g_ks; bb0 = g_spk[b*64+h]; bb1 = g_spk[b*64+h+1]; }
                else        { dst = g_vs; bb0 = g_spv[b*64+h]; bb1 = g_spv[b*64+h+1]; }
                rl = true;
            } else {
                if (c < 64) { dst = g_xq; bb0 = 0.f; bb1 = 0.f; }
                else        { dst = g_t1; bb0 = tab[h]; bb1 = tab[h+1]; }
                rl = false;
            }
            #pragma unroll
            for (int half_ = 0; half_ < 2; half_++) {
                int r = r0 + mm*16 + half_*8;
                float v0 = acc[mm][nn][half_*2+0] + bb0;
                float v1 = acc[mm][nn][half_*2+1] + bb1;
                if (rl) { v0 = fmaxf(v0, 0.f); v1 = fmaxf(v1, 0.f); }
                *(float2*)(dst + ((long long)b*NN + r)*64 + h) = make_float2(v0, v1);
            }
        }
}

// ------- attention tail: logits/softmax/rank-8 combine -> de_input -------
__global__ void k_attn3_full(const float* __restrict__ taw) {
    int n = blockIdx.x, b = blockIdx.y;
    int tid = threadIdx.x;             // 128
    __shared__ float xq[64], ks[64], vs[64], t1[64], lg[96], us[8][64], sqs[TT*64];

    long long row = ((long long)b*NN + n)*64;
    if (tid < 64) { xq[tid] = g_xq[row+tid]; ks[tid] = g_ks[row+tid]; }
    else { int h = tid-64; vs[h] = g_vs[row+h]; t1[h] = g_t1[row+h]; }
    for (int i = tid; i < TT*64; i += 128) sqs[i] = g_sqq[b*TT*64 + i];
    __syncthreads();

    if (tid < 96) {                    // logits per (head d, time t)
        int d = tid / 12, t = tid % 12;
        float a = 0.f;
        #pragma unroll
        for (int c = 0; c < 8; c++) {
            int h = d*8 + c;
            float q = fmaxf(xq[h] + sqs[t*64+h], 0.f);
            a = fmaf(q, ks[h], a);
        }
        lg[d*12+t] = a;
    }
    __syncthreads();
    if (tid < 8) {                     // softmax over t
        int d = tid;
        float mx = -1e30f;
        for (int t = 0; t < 12; t++) mx = fmaxf(mx, lg[d*12+t]);
        float s = 0.f;
        for (int t = 0; t < 12; t++) { float e = expf(lg[d*12+t]-mx); lg[d*12+t] = e; s += e; }
        float inv = 1.f/s;
        for (int t = 0; t < 12; t++) lg[d*12+t] *= inv;
    }
    __syncthreads();
    for (int idx = tid; idx < 512; idx += 128) {    // us[d][h] = sum_i vs[i]*taw2[i][h]
        int d = idx >> 6, h = idx & 63;
        float a = 0.f;
        #pragma unroll
        for (int c = 0; c < 8; c++) {
            int i = d*8 + c;
            a = fmaf(vs[i], taw[4096 + i*64 + h], a);
        }
        us[d][h] = a;
    }
    __syncthreads();
    for (int idx = tid; idx < TT*64; idx += 128) {
        int t = idx >> 6, h = idx & 63;
        float a = t1[h];
        #pragma unroll
        for (int d = 0; d < 8; d++) a = fmaf(lg[d*12+t], us[d][h], a);
        long long o = ((long long)(b*12+t)*NN + n)*HH + h;
        g_de[o]  = a;
        g_deh[o] = __float2half_rn(a);
    }
}

// ---- per-(b,t) weights (scalar, known good): temb@B + bias ---------------
// mode 0: gwp->g_W1h  1: uwp->g_W2h  2: gbp->g_b1  3: ubp->g_b2
__global__ void k_wgemm(const float* __restrict__ Am, const float* __restrict__ Bm,
                        const float* __restrict__ bias, int mode) {
    __half* Ch = nullptr; float* Cf = nullptr; int Nc;
    if (mode == 0)      { Ch = g_W1h; Nc = 3*65*O1; }
    else if (mode == 1) { Ch = g_W2h; Nc = 3*65*O2; }
    else if (mode == 2) { Cf = g_b1; Nc = O1; }
    else                { Cf = g_b2; Nc = O2; }

    __shared__ float At[32][65];
    __shared__ float Bt[32][64];
    int q0 = blockIdx.x * 64;
    int m0 = blockIdx.y * 64;
    int tid = threadIdx.x;
    int tx = tid & 15, ty = tid >> 4;
    #pragma unroll
    for (int p=0;p<8;p++) {
        int idx = tid + p*256;
        int d = idx & 31, m = idx >> 5;
        At[d][m] = Am[(m0+m)*32 + d];
    }
    #pragma unroll
    for (int p=0;p<8;p++) {
        int idx = tid + p*256;
        int q = idx & 63, d = idx >> 6;
        Bt[d][q] = Bm[(long long)d*Nc + q0 + q];
    }
    __syncthreads();
    float acc[4][4] = {};
    #pragma unroll
    for (int d=0; d<32; d++) {
        float a[4];
        #pragma unroll
        for (int i=0;i<4;i++) a[i] = At[d][ty*4+i];
        float4 b4 = *(const float4*)&Bt[d][tx*4];
        float bv[4] = {b4.x,b4.y,b4.z,b4.w};
        #pragma unroll
        for (int i=0;i<4;i++)
            #pragma unroll
            for (int j=0;j<4;j++) acc[i][j] = fmaf(a[i], bv[j], acc[i][j]);
    }
    float4 bb = *(const float4*)&bias[q0 + tx*4];
    float bs[4] = {bb.x,bb.y,bb.z,bb.w};
    #pragma unroll
    for (int i=0;i<4;i++) {
        float v0 = acc[i][0]+bs[0], v1 = acc[i][1]+bs[1];
        float v2 = acc[i][2]+bs[2], v3 = acc[i][3]+bs[3];
        long long off = (long long)(m0+ty*4+i)*Nc + q0 + tx*4;
        if (Ch) {
            *(__half2*)(Ch + off)     = __floats2half2_rn(v0, v1);
            *(__half2*)(Ch + off + 2) = __floats2half2_rn(v2, v3);
        } else {
            *(float4*)(Cf + off) = make_float4(v0, v1, v2, v3);
        }
    }
}

// ======== gcn1 (fp16 mma): zr = sigmoid(xg@W1+b1) -> yh = z*de, rg ========
__global__ void __launch_bounds__(256) k_gcn1_mma() {
    __shared__ __align__(16) __half As[128][40];
    __shared__ __align__(16) __half Ws[32][136];
    int tid = threadIdx.x;
    int wid = tid >> 5, lane = tid & 31;
    int warpR = wid >> 1, warpC = wid & 1;
    int n0 = blockIdx.x * 128;
    int b  = blockIdx.y;
    const __half* srcs[3] = { g_deh + (long long)b*PS, g_p1h + (long long)b*PS, g_p2h + (long long)b*PS };
    const __half* WB = g_W1h + (long long)b*3*65*O1;

    float acc[2][8][4];
    #pragma unroll
    for (int mm=0;mm<2;mm++)
        #pragma unroll
        for (int nn=0;nn<8;nn++)
            #pragma unroll
            for (int q=0;q<4;q++) acc[mm][nn][q] = 0.f;

    int lrow = lane & 15, lcol = (lane >> 4) << 3;

    for (int kc = 0; kc < 6; kc++) {
        int k = kc >> 1, c0 = (kc & 1) * 32;
        const __half* S = srcs[k];
        #pragma unroll
        for (int it = 0; it < 2; it++) {
            int idx = tid + it * 256;
            int r = idx >> 2, f = idx & 3;
            *(uint4*)&As[r][f*8] = *(const uint4*)(S + (long long)(n0+r)*HH + c0 + f*8);
        }
        #pragma unroll
        for (int it = 0; it < 2; it++) {
            int idx = tid + it * 256;
            int j = idx >> 4, f = idx & 15;
            *(uint4*)&Ws[j][f*8] = *(const uint4*)(WB + (long long)(k*65 + 1 + c0 + j)*O1 + f*8);
        }
        __syncthreads();
        #pragma unroll
        for (int k16 = 0; k16 < 2; k16++) {
            uint32_t a[2][4];
            #pragma unroll
            for (int mm = 0; mm < 2; mm++)
                ldsm_x4(a[mm], s2u(&As[warpR*32 + mm*16 + lrow][k16*16 + lcol]));
            #pragma unroll
            for (int g = 0; g < 4; g++) {
                uint32_t bf[4];
                ldsm_x4_t(bf, s2u(&Ws[k16*16 + lrow][warpC*64 + g*16 + lcol]));
                #pragma unroll
                for (int mm = 0; mm < 2; mm++) {
                    mma_f16(acc[mm][g*2+0], a[mm], &bf[0]);
                    mma_f16(acc[mm][g*2+1], a[mm], &bf[2]);
                }
            }
        }
        __syncthreads();
    }

    const float* b1B = g_b1 + b*O1;
    const float* deB = g_de + (long long)b*PS;
    __half* yB = g_yh + (long long)b*PS;
    float* rgB = g_rg + (long long)b*PS;
    int r0 = n0 + warpR * 32 + (lane >> 2);
    int co = warpC * 64 + 2 * (lane & 3);
    #pragma unroll
    for (int mm = 0; mm < 2; mm++)
        #pragma unroll
        for (int nn = 0; nn < 8; nn++) {
            int o = co + nn*8;
            float bb0 = b1B[o], bb1 = b1B[o+1];
            #pragma unroll
            for (int half_ = 0; half_ < 2; half_++) {
                int r = r0 + mm*16 + half_*8;
                float s0 = 1.f/(1.f + expf(-(acc[mm][nn][half_*2+0] + bb0)));
                float s1 = 1.f/(1.f + expf(-(acc[mm][nn][half_*2+1] + bb1)));
                if (warpC == 0) {
                    float2 d = *(const float2*)(deB + (long long)r*HH + o);
                    *(__half2*)(yB + (long long)r*HH + o) = __floats2half2_rn(s0*d.x, s1*d.y);
                } else {
                    *(float2*)(rgB + (long long)r*HH + (o-64)) = make_float2(s0, s1);
                }
            }
        }
}

// ======== gcn2 (fp16 mma): hc = tanh(.), GRU state, time projection =======
__global__ void __launch_bounds__(256) k_gcn2_mma(const float* __restrict__ ow,
                                                  const float* __restrict__ ob,
                                                  float* __restrict__ dout) {
    __shared__ __align__(16) union {
        struct { __half As[128][40]; __half Ws[32][72]; } ld;
        float st[128][65];
    } sm;
    int tid = threadIdx.x;
    int wid = tid >> 5, lane = tid & 31;
    int warpR = wid >> 1, warpC = wid & 1;
    int n0 = blockIdx.x * 128;
    int b  = blockIdx.y;
    const __half* srcs[3] = { g_yh + (long long)b*PS, g_p1h + (long long)b*PS, g_p2h + (long long)b*PS };
    const __half* WB = g_W2h + (long long)b*3*65*O2;

    float acc[2][4][4];
    #pragma unroll
    for (int mm=0;mm<2;mm++)
        #pragma unroll
        for (int nn=0;nn<4;nn++)
            #pragma unroll
            for (int q=0;q<4;q++) acc[mm][nn][q] = 0.f;

    int lrow = lane & 15, lcol = (lane >> 4) << 3;

    for (int kc = 0; kc < 6; kc++) {
        int k = kc >> 1, c0 = (kc & 1) * 32;
        const __half* S = srcs[k];
        #pragma unroll
        for (int it = 0; it < 2; it++) {
            int idx = tid + it * 256;
            int r = idx >> 2, f = idx & 3;
            *(uint4*)&sm.ld.As[r][f*8] = *(const uint4*)(S + (long long)(n0+r)*HH + c0 + f*8);
        }
        {
            int j = tid >> 3, f = tid & 7;
            *(uint4*)&sm.ld.Ws[j][f*8] = *(const uint4*)(WB + (long long)(k*65 + 1 + c0 + j)*O2 + f*8);
        }
        __syncthreads();
        #pragma unroll
        for (int k16 = 0; k16 < 2; k16++) {
            uint32_t a[2][4], bf[2][4];
            #pragma unroll
            for (int mm = 0; mm < 2; mm++)
                ldsm_x4(a[mm], s2u(&sm.ld.As[warpR*32 + mm*16 + lrow][k16*16 + lcol]));
            #pragma unroll
            for (int g = 0; g < 2; g++)
                ldsm_x4_t(bf[g], s2u(&sm.ld.Ws[k16*16 + lrow][warpC*32 + g*16 + lcol]));
            #pragma unroll
            for (int mm = 0; mm < 2; mm++)
                #pragma unroll
                for (int g = 0; g < 2; g++) {
                    mma_f16(acc[mm][g*2+0], a[mm], &bf[g][0]);
                    mma_f16(acc[mm][g*2+1], a[mm], &bf[g][2]);
                }
        }
        __syncthreads();
    }

    const float* b2B = g_b2 + b*O2;
    const float* deB = g_de + (long long)b*PS;
    const float* rgB = g_rg + (long long)b*PS;
    int r0l = warpR * 32 + (lane >> 2);
    int co = warpC * 32 + 2 * (lane & 3);
    #pragma unroll
    for (int mm = 0; mm < 2; mm++)
        #pragma unroll
        for (int nn = 0; nn < 4; nn++) {
            int o = co + nn*8;
            float bb0 = b2B[o], bb1 = b2B[o+1];
            #pragma unroll
            for (int half_ = 0; half_ < 2; half_++) {
                int rl = r0l + mm*16 + half_*8;
                int n = n0 + rl;
                float h0 = tanhf(acc[mm][nn][half_*2+0] + bb0);
                float h1 = tanhf(acc[mm][nn][half_*2+1] + bb1);
                float2 rr = *(const float2*)(rgB + (long long)n*HH + o);
                float2 dd = *(const float2*)(deB + (long long)n*HH + o);
                sm.st[rl][o]   = rr.x*dd.x + (1.f - rr.x)*h0;
                sm.st[rl][o+1] = rr.y*dd.y + (1.f - rr.y)*h1;
            }
        }
    __syncthreads();

    int t = b % 12, bo = b / 12;
    if (tid < 128) {
        int nl = tid;
        float a = ob[t];
        #pragma unroll
        for (int h = 0; h < 64; h++) a = fmaf(sm.st[nl][h], ow[t*64+h], a);
        dout[(long long)bo*TT*NN + t*NN + n0 + nl] = a;
    }
}

// -------------------------------------------------------------------------
extern "C" void kernel_launch(void* const* d_in, const int* in_sizes, int n_in,
                              void* d_out, int out_size) {
    const float* hn  = (const float*)d_in[2];
    const float* ne1 = (const float*)d_in[3];
    const float* ne2 = (const float*)d_in[4];
    const float* E   = (const float*)d_in[5];
    const float* Wq  = (const float*)d_in[6];
    const float* bq  = (const float*)d_in[7];
    const float* Wk  = (const float*)d_in[8];
    const float* bk  = (const float*)d_in[9];
    const float* Wv  = (const float*)d_in[10];
    const float* bv  = (const float*)d_in[11];
    const float* taw = (const float*)d_in[12];
    const float* tab = (const float*)d_in[13];
    const float* gwp = (const float*)d_in[14];
    const float* gw  = (const float*)d_in[15];
    const float* gbp = (const float*)d_in[16];
    const float* gb  = (const float*)d_in[17];
    const float* uwp = (const float*)d_in[18];
    const float* uw  = (const float*)d_in[19];
    const float* ubp = (const float*)d_in[20];
    const float* ub  = (const float*)d_in[21];
    const float* ow  = (const float*)d_in[22];
    const float* ob  = (const float*)d_in[23];
    float* out = (float*)d_out;

    dim3 gprop(8, BT/2);       // 2 slices per CTA
    dim3 ggcn (NN/128, BT);

    k_adj<<<512, 512>>>(E);                                                 // 1
    k_a2<<<dim3(4, 4), 256>>>();                                            // 2
    k_attn_pre<<<BB, 64>>>(ne1, ne2, Wq, bq, Wk, bk, Wv, bv);               // 3
    k_qkv<<<dim3(4, 2, BB), 256>>>(hn, Wq, Wk, Wv, taw, tab);               // 4
    k_attn3_full<<<dim3(NN, BB), 128>>>(taw);                               // 5
    k_prop2<<<gprop, 256>>>(1);                                  // profiled 6
    k_wgemm<<<dim3((3*65*O1)/64, BT/64), 256>>>(ne2, gwp, gw, 0);
    k_wgemm<<<dim3((3*65*O2)/64, BT/64), 256>>>(ne2, uwp, uw, 1);
    k_wgemm<<<dim3(O1/64, BT/64), 256>>>(ne2, gbp, gb, 2);
    k_wgemm<<<dim3(O2/64, BT/64), 256>>>(ne2, ubp, ub, 3);
    k_gcn1_mma<<<ggcn, 256>>>();
    k_prop2<<<gprop, 256>>>(2);
    k_gcn2_mma<<<ggcn, 256>>>(ow, ob, out);
}